// round 8
// baseline (speedup 1.0000x reference)
#include <cuda_runtime.h>
#include <cuda_fp16.h>
#include <cstdint>

#define NB   8
#define NC   64
#define NH   64
#define NW   192
#define NP   20

__device__ float g_bufA[NB * NP * NP * NH * NW];
__device__ float g_bufB[NB * NP * NP * NH * NW];

__device__ __forceinline__ float leaky(float x) {
    return x > 0.0f ? x : 0.1f * x;
}

// ---- typed vector IO (fp32 or fp16 storage, fp32 compute) -----------------
template<typename T> struct VIO;
template<> struct VIO<float> {
    static __device__ __forceinline__ float4 ld4(const float* p) { return *(const float4*)p; }
    static __device__ __forceinline__ void st4(float* p, float4 v) { *(float4*)p = v; }
    static __device__ __forceinline__ float ld1(const float* p) { return *p; }
};
template<> struct VIO<__half> {
    static __device__ __forceinline__ float4 ld4(const __half* p) {
        __half2 h0 = *(const __half2*)p;
        __half2 h1 = *(const __half2*)(p + 2);
        float2 f0 = __half22float2(h0), f1 = __half22float2(h1);
        return make_float4(f0.x, f0.y, f1.x, f1.y);
    }
    static __device__ __forceinline__ void st4(__half* p, float4 v) {
        *(__half2*)p       = __floats2half2_rn(v.x, v.y);
        *(__half2*)(p + 2) = __floats2half2_rn(v.z, v.w);
    }
    static __device__ __forceinline__ float ld1(const __half* p) { return __half2float(*p); }
};

// ---- packed f32x2 helpers (sm_103a) --------------------------------------
__device__ __forceinline__ unsigned long long pk2(float lo, float hi) {
    unsigned long long r;
    asm("mov.b64 %0, {%1, %2};" : "=l"(r) : "f"(lo), "f"(hi));
    return r;
}
__device__ __forceinline__ void fma2(unsigned long long& d,
                                     unsigned long long a,
                                     unsigned long long b) {
    asm("fma.rn.f32x2 %0, %1, %2, %0;" : "+l"(d) : "l"(a), "l"(b));
}
__device__ __forceinline__ float2 upk(unsigned long long v) {
    float2 f;
    asm("mov.b64 {%0, %1}, %2;" : "=f"(f.x), "=f"(f.y) : "l"(v));
    return f;
}

// ---------------------------------------------------------------------------
// Correlation: block = (h, di-pair, b), 128 threads (96 active).
// Active thread: r = di-pair half, tile 8 w x 10 dj, f32x2 accumulators.
// Channels in 4 chunks of 16. smem = 16*192 + 2*16*212 floats = 39.4 KB.
// Invalid depth rows become zero planes -> outputs naturally zero.
// ---------------------------------------------------------------------------
__global__ void __launch_bounds__(128, 4)
corr_kernel(const float* __restrict__ rgb,
            const float* __restrict__ dep,
            __half* __restrict__ out)
{
    const int h  = blockIdx.x;
    const int dp = blockIdx.y;          // di = 2*dp + r
    const int b  = blockIdx.z;
    const int tid = threadIdx.x;

    __shared__ __align__(16) float sm_rgb[16 * 192];
    __shared__ __align__(16) float sm_dep[2 * 16 * 212];  // [r][c][x], x=w+dj

    const int r   = tid / 48;           // 0..1 (active)
    const int it  = tid % 48;
    const int wg  = it % 24;
    const int djg = it / 24;
    const int w0  = wg * 8;
    const int dj0 = djg * 10;
    const int x0  = w0 + dj0;           // even
    const bool active = (tid < 96);

    const int hr0 = h + 2 * dp - 10;
    const int hr1 = hr0 + 1;
    const bool v0 = (hr0 >= 0 && hr0 < NH);
    const bool v1 = (hr1 >= 0 && hr1 < NH);

    if (!v0 && !v1) {
        if (active) {
            uint4 z = {0u, 0u, 0u, 0u};
            #pragma unroll
            for (int j = 0; j < 10; j++) {
                size_t base = ((((size_t)b * NP + 2 * dp + r) * NP + dj0 + j) * NH + h) * NW + w0;
                *(uint4*)&out[base] = z;
            }
        }
        return;
    }

    unsigned long long acc2[10][4];
    #pragma unroll
    for (int j = 0; j < 10; j++)
        #pragma unroll
        for (int p = 0; p < 4; p++) acc2[j][p] = 0ull;

    const size_t bbase = (size_t)b * NC * NH * NW;

    #pragma unroll 1
    for (int cc = 0; cc < 4; cc++) {
        const int c0 = cc * 16;
        if (cc) __syncthreads();

        // rgb chunk: 768 float4, 6 per thread
        #pragma unroll
        for (int u = 0; u < 6; u++) {
            int i = tid + u * 128;
            int c = i / 48;
            int k4 = (i - c * 48) * 4;
            *(float4*)&sm_rgb[c * 192 + k4] =
                *(const float4*)&rgb[bbase + (size_t)(c0 + c) * (NH * NW) + h * NW + k4];
        }
        // dep interior: 2 rows x 16 ch x 48 float4 = 1536, 12 per thread
        #pragma unroll
        for (int u = 0; u < 12; u++) {
            int i = tid + u * 128;
            int rc = i / 48;                 // 0..31
            int k4 = (i - rc * 48) * 4;
            int rr = rc >> 4;
            int c  = rc & 15;
            int hr = rr ? hr1 : hr0;
            bool vr = rr ? v1 : v0;
            float4 v = {0.f, 0.f, 0.f, 0.f};
            if (vr)
                v = *(const float4*)&dep[bbase + (size_t)(c0 + c) * (NH * NW) + hr * NW + k4];
            float* dst = &sm_dep[rc * 212 + 10 + k4];
            *(float2*)(dst)     = make_float2(v.x, v.y);
            *(float2*)(dst + 2) = make_float2(v.z, v.w);
        }
        // dep edges: 2*16*20 = 640, 5 per thread
        #pragma unroll
        for (int u = 0; u < 5; u++) {
            int i = tid + u * 128;
            int rc = i / 20;
            int p = i - rc * 20;
            int x = (p < 10) ? p : 192 + p;
            sm_dep[rc * 212 + x] = 0.0f;
        }
        __syncthreads();

        if (!active) continue;

        #pragma unroll 2
        for (int c = 0; c < 16; c++) {
            const float* rp = &sm_rgb[c * 192 + w0];
            float4 ra = *(const float4*)rp;
            float4 rb = *(const float4*)(rp + 4);
            unsigned long long r2[4] = {
                pk2(ra.x, ra.y), pk2(ra.z, ra.w),
                pk2(rb.x, rb.y), pk2(rb.z, rb.w)
            };
            const float2* dpt = (const float2*)&sm_dep[(r * 16 + c) * 212 + x0];
            float2 dv2[9];
            #pragma unroll
            for (int k = 0; k < 9; k++) dv2[k] = dpt[k];

            #pragma unroll
            for (int j = 0; j < 10; j++) {
                if ((j & 1) == 0) {
                    #pragma unroll
                    for (int p = 0; p < 4; p++) {
                        unsigned long long d = pk2(dv2[p + j / 2].x, dv2[p + j / 2].y);
                        fma2(acc2[j][p], r2[p], d);
                    }
                } else {
                    #pragma unroll
                    for (int p = 0; p < 4; p++) {
                        unsigned long long d = pk2(dv2[p + (j - 1) / 2].y,
                                                   dv2[p + (j + 1) / 2].x);
                        fma2(acc2[j][p], r2[p], d);
                    }
                }
            }
        }
    }

    if (!active) return;
    #pragma unroll
    for (int j = 0; j < 10; j++) {
        float2 f0 = upk(acc2[j][0]);
        float2 f1 = upk(acc2[j][1]);
        float2 f2 = upk(acc2[j][2]);
        float2 f3 = upk(acc2[j][3]);
        size_t base = ((((size_t)b * NP + 2 * dp + r) * NP + dj0 + j) * NH + h) * NW + w0;
        __half2 hh[4] = {
            __floats2half2_rn(f0.x, f0.y), __floats2half2_rn(f1.x, f1.y),
            __floats2half2_rn(f2.x, f2.y), __floats2half2_rn(f3.x, f3.y)
        };
        *(uint4*)&out[base] = *(uint4*)hh;
    }
}

// ---------------------------------------------------------------------------
// Depthwise 3x3x3, stride 1, pad 1, + leaky. Rolling-z: block = (n, c, h-tile),
// loops d with a 3-plane smem ring -> each input plane loaded once.
// ---------------------------------------------------------------------------
template<int C, int D, int H, int W, int HT, typename Tin, typename Tout>
__global__ void dw_s1_kernel(const Tin* __restrict__ in,
                             const float* __restrict__ wgt,
                             const float* __restrict__ bias,
                             Tout* __restrict__ out)
{
    constexpr int SW = W + 8;
    constexpr int WQ = W / 4;
    __shared__ float smp[3][18 * SW];

    int bx = blockIdx.x;
    const int ht = bx % HT;  bx /= HT;
    const int c  = bx % C;
    const int n  = bx / C;
    const int h0 = ht * 16;
    const int tid = threadIdx.x;

    const Tin* inb = in + (size_t)(n * C + c) * D * H * W;
    Tout* outb = out + (size_t)(n * C + c) * D * H * W;

    float wt[27];
    #pragma unroll
    for (int k = 0; k < 27; k++) wt[k] = __ldg(&wgt[c * 27 + k]);
    const float bb = __ldg(&bias[c]);

    // zero x-pads of all 3 planes once (interior fills never touch them)
    for (int i = tid; i < 3 * 18 * 8; i += blockDim.x) {
        int row = i / 8;
        int p   = i - row * 8;
        int x   = (p < 4) ? p : W + p;
        smp[row / 18][(row % 18) * SW + x] = 0.0f;
    }

    // plane loader: zi -> slot
    auto load_plane = [&](int slot, int zi) {
        for (int i = tid; i < 18 * WQ; i += blockDim.x) {
            int y  = i / WQ;
            int k4 = (i - y * WQ) * 4;
            int yi = h0 - 1 + y;
            float4 v = {0.f, 0.f, 0.f, 0.f};
            if (zi >= 0 && zi < D && yi >= 0 && yi < H)
                v = VIO<Tin>::ld4(&inb[(size_t)zi * H * W + yi * W + k4]);
            *(float4*)&smp[slot][y * SW + 4 + k4] = v;
        }
    };

    load_plane(0, -1);
    load_plane(1, 0);
    __syncthreads();

    #pragma unroll 1
    for (int d = 0; d < D; d++) {
        load_plane((d + 2) % 3, d + 1);
        __syncthreads();

        const float* pl[3] = { smp[d % 3], smp[(d + 1) % 3], smp[(d + 2) % 3] };

        constexpr int items = 16 * WQ;
        for (int it = tid; it < items; it += blockDim.x) {
            int hl  = it / WQ;
            int wg4 = (it - hl * WQ) * 4;
            float a0 = bb, a1 = bb, a2 = bb, a3 = bb;
            #pragma unroll
            for (int z = 0; z < 3; z++)
                #pragma unroll
                for (int y = 0; y < 3; y++) {
                    const float* row = &pl[z][(hl + y) * SW];
                    float m1  = row[wg4 + 3];
                    float4 v4 = *(const float4*)&row[wg4 + 4];
                    float p   = row[wg4 + 8];
                    float w0 = wt[(z * 3 + y) * 3 + 0];
                    float w1 = wt[(z * 3 + y) * 3 + 1];
                    float w2 = wt[(z * 3 + y) * 3 + 2];
                    a0 += w0 * m1   + w1 * v4.x + w2 * v4.y;
                    a1 += w0 * v4.x + w1 * v4.y + w2 * v4.z;
                    a2 += w0 * v4.y + w1 * v4.z + w2 * v4.w;
                    a3 += w0 * v4.z + w1 * v4.w + w2 * p;
                }
            float4 o = {leaky(a0), leaky(a1), leaky(a2), leaky(a3)};
            VIO<Tout>::st4(&outb[(size_t)d * H * W + (h0 + hl) * W + wg4], o);
        }
        __syncthreads();
    }
}

// ---------------------------------------------------------------------------
// Depthwise 3x3x3, stride 2, pad 1, + leaky. Thread = 4 consecutive wo.
// ---------------------------------------------------------------------------
template<int C, int D, int H, int W, int Do, int Ho, int Wo, typename Tin, typename Tout>
__global__ void dw_s2_kernel(const Tin* __restrict__ in,
                             const float* __restrict__ wgt,
                             const float* __restrict__ bias,
                             Tout* __restrict__ out)
{
    constexpr int WQ = Wo / 4;
    constexpr int total = NB * C * Do * Ho * WQ;
    int idx = blockIdx.x * blockDim.x + threadIdx.x;
    if (idx >= total) return;
    int t = idx;
    const int q  = t % WQ; t /= WQ;
    const int ho = t % Ho; t /= Ho;
    const int dd = t % Do; t /= Do;
    const int c  = t % C;
    const int n  = t / C;
    const int g  = q * 8;

    const Tin* inb = in + (size_t)(n * C + c) * D * H * W;
    const float* wp  = &wgt[c * 27];
    const float bb = __ldg(&bias[c]);
    float a0 = bb, a1 = bb, a2 = bb, a3 = bb;

    #pragma unroll
    for (int kz = 0; kz < 3; kz++) {
        int zi = 2 * dd - 1 + kz;
        if (zi < 0 || zi >= D) continue;
        #pragma unroll
        for (int ky = 0; ky < 3; ky++) {
            int yi = 2 * ho - 1 + ky;
            if (yi < 0 || yi >= H) continue;
            const Tin* base = &inb[(size_t)zi * H * W + yi * W];
            float  m1 = (g > 0) ? VIO<Tin>::ld1(&base[g - 1]) : 0.0f;
            float4 v0 = VIO<Tin>::ld4(&base[g]);
            float4 v1 = VIO<Tin>::ld4(&base[g + 4]);
            float xv[9] = {m1, v0.x, v0.y, v0.z, v0.w, v1.x, v1.y, v1.z, v1.w};
            float w0 = __ldg(&wp[(kz * 3 + ky) * 3 + 0]);
            float w1 = __ldg(&wp[(kz * 3 + ky) * 3 + 1]);
            float w2 = __ldg(&wp[(kz * 3 + ky) * 3 + 2]);
            a0 += w0 * xv[0] + w1 * xv[1] + w2 * xv[2];
            a1 += w0 * xv[2] + w1 * xv[3] + w2 * xv[4];
            a2 += w0 * xv[4] + w1 * xv[5] + w2 * xv[6];
            a3 += w0 * xv[6] + w1 * xv[7] + w2 * xv[8];
        }
    }
    float4 o = {leaky(a0), leaky(a1), leaky(a2), leaky(a3)};
    size_t obase = ((((size_t)n * C + c) * Do + dd) * Ho + ho) * Wo + q * 4;
    VIO<Tout>::st4(&out[obase], o);
}

// ---------------------------------------------------------------------------
// Pointwise Cin->Cout + leaky. f32x2 accumulators, packed duplicated weights
// in smem (LDS.64 broadcast). Thread = 4 positions x COT co.
// ---------------------------------------------------------------------------
template<int Cin, int COT, typename Tin, typename Tout>
__global__ void pw_kernel(const Tin* __restrict__ in,
                          const float* __restrict__ wgt,
                          const float* __restrict__ bias,
                          Tout* __restrict__ out,
                          int Cout, int plane, int nquad)
{
    __shared__ unsigned long long sw2[COT * Cin];
    __shared__ float sb[COT];

    const int co0 = blockIdx.y * COT;
    const int tid = threadIdx.x;

    for (int i = tid; i < COT * Cin; i += blockDim.x) {
        int j  = i / Cin;
        int ci = i - j * Cin;
        float wv = wgt[(co0 + j) * Cin + ci];
        sw2[i] = pk2(wv, wv);
    }
    if (tid < COT) sb[tid] = bias[co0 + tid];
    __syncthreads();

    const int t = blockIdx.x * blockDim.x + tid;
    if (t >= nquad) return;
    const int s0 = t * 4;
    const int n  = s0 / plane;
    const int p  = s0 - n * plane;

    const Tin* inb = in + (size_t)n * Cin * plane + p;

    unsigned long long acc2[COT][2];
    #pragma unroll
    for (int j = 0; j < COT; j++) {
        float bv = sb[j];
        unsigned long long bp = pk2(bv, bv);
        acc2[j][0] = bp; acc2[j][1] = bp;
    }

    #pragma unroll
    for (int ci = 0; ci < Cin; ci++) {
        float4 x4 = VIO<Tin>::ld4(&inb[(size_t)ci * plane]);
        unsigned long long xa = pk2(x4.x, x4.y);
        unsigned long long xb = pk2(x4.z, x4.w);
        #pragma unroll
        for (int j = 0; j < COT; j++) {
            unsigned long long wv2 = sw2[j * Cin + ci];
            fma2(acc2[j][0], wv2, xa);
            fma2(acc2[j][1], wv2, xb);
        }
    }

    Tout* ob = out + (size_t)n * Cout * plane + p;
    #pragma unroll
    for (int j = 0; j < COT; j++) {
        float2 fa = upk(acc2[j][0]);
        float2 fb = upk(acc2[j][1]);
        float4 o = {leaky(fa.x), leaky(fa.y), leaky(fb.x), leaky(fb.y)};
        VIO<Tout>::st4(&ob[(size_t)(co0 + j) * plane], o);
    }
}

// ---------------------------------------------------------------------------
extern "C" void kernel_launch(void* const* d_in, const int* in_sizes, int n_in,
                              void* d_out, int out_size)
{
    const float* rgb   = (const float*)d_in[0];
    const float* dep   = (const float*)d_in[1];
    const float* dw1_w = (const float*)d_in[2];
    const float* dw1_b = (const float*)d_in[3];
    const float* pw1_w = (const float*)d_in[4];
    const float* pw1_b = (const float*)d_in[5];
    const float* dw2_w = (const float*)d_in[6];
    const float* dw2_b = (const float*)d_in[7];
    const float* pw2_w = (const float*)d_in[8];
    const float* pw2_b = (const float*)d_in[9];
    const float* dw3_w = (const float*)d_in[10];
    const float* dw3_b = (const float*)d_in[11];
    const float* pw3_w = (const float*)d_in[12];
    const float* pw3_b = (const float*)d_in[13];
    const float* dw4_w = (const float*)d_in[14];
    const float* dw4_b = (const float*)d_in[15];
    const float* pw4_w = (const float*)d_in[16];
    const float* pw4_b = (const float*)d_in[17];
    float* out = (float*)d_out;

    float *bufA = nullptr, *bufB = nullptr;
    cudaGetSymbolAddress((void**)&bufA, g_bufA);
    cudaGetSymbolAddress((void**)&bufB, g_bufB);
    __half* bufA_h = (__half*)bufA;
    __half* bufB_h = (__half*)bufB;

    // ---- correlation -> bufA (fp16) ----
    corr_kernel<<<dim3(NH, NP / 2, NB), 128>>>(rgb, dep, bufA_h);

    // ---- block 1 (stride 1): dw 20ch rolling-z (fp16->fp16), pw 20->20 ----
    dw_s1_kernel<20, 20, 64, 192, 4, __half, __half>
        <<<NB * 20 * 4, 256>>>(bufA_h, dw1_w, dw1_b, bufB_h);
    {
        const int plane = 20 * 64 * 192;
        const int nquad = NB * plane / 4;
        pw_kernel<20, 20, __half, __half>
            <<<dim3((nquad + 255) / 256, 1), 256>>>(bufB_h, pw1_w, pw1_b, bufA_h,
                                                    20, plane, nquad);
    }

    // ---- block 2 (stride 2): dw (fp16->fp32) -> (20,10,32,96), pw 20->40 ----
    {
        const int threads = NB * 20 * 10 * 32 * (96 / 4);
        dw_s2_kernel<20, 20, 64, 192, 10, 32, 96, __half, float>
            <<<(threads + 255) / 256, 256>>>(bufA_h, dw2_w, dw2_b, bufB);
        const int plane = 10 * 32 * 96;
        const int nquad = NB * plane / 4;
        pw_kernel<20, 20, float, float>
            <<<dim3((nquad + 255) / 256, 2), 256>>>(bufB, pw2_w, pw2_b, bufA,
                                                    40, plane, nquad);
    }

    // ---- block 3 (stride 1): dw 40ch rolling-z on (10,32,96), pw 40->40 ----
    dw_s1_kernel<40, 10, 32, 96, 2, float, float>
        <<<NB * 40 * 2, 256>>>(bufA, dw3_w, dw3_b, bufB);
    {
        const int plane = 10 * 32 * 96;
        const int nquad = NB * plane / 4;
        pw_kernel<40, 20, float, float>
            <<<dim3((nquad + 255) / 256, 2), 256>>>(bufB, pw3_w, pw3_b, bufA,
                                                    40, plane, nquad);
    }

    // ---- block 4 (stride 2): dw -> (40,5,16,48), pw 40->80 -> d_out ----
    {
        const int threads = NB * 40 * 5 * 16 * (48 / 4);
        dw_s2_kernel<40, 10, 32, 96, 5, 16, 48, float, float>
            <<<(threads + 255) / 256, 256>>>(bufA, dw4_w, dw4_b, bufB);
        const int plane = 5 * 16 * 48;
        const int nquad = NB * plane / 4;
        pw_kernel<40, 20, float, float>
            <<<dim3((nquad + 255) / 256, 4), 256>>>(bufB, pw4_w, pw4_b, out,
                                                    80, plane, nquad);
    }
}

// round 9
// speedup vs baseline: 1.0871x; 1.0871x over previous
#include <cuda_runtime.h>
#include <cuda_fp16.h>
#include <cstdint>

#define NB   8
#define NC   64
#define NH   64
#define NW   192
#define NP   20

__device__ float g_bufA[NB * NP * NP * NH * NW];
__device__ float g_bufB[NB * NP * NP * NH * NW];

__device__ __forceinline__ float leaky(float x) {
    return x > 0.0f ? x : 0.1f * x;
}

// ---- typed vector IO (fp32 or fp16 storage, fp32 compute) -----------------
template<typename T> struct VIO;
template<> struct VIO<float> {
    static __device__ __forceinline__ float4 ld4(const float* p) { return *(const float4*)p; }
    static __device__ __forceinline__ void st4(float* p, float4 v) { *(float4*)p = v; }
    static __device__ __forceinline__ float ld1(const float* p) { return *p; }
};
template<> struct VIO<__half> {
    static __device__ __forceinline__ float4 ld4(const __half* p) {
        __half2 h0 = *(const __half2*)p;
        __half2 h1 = *(const __half2*)(p + 2);
        float2 f0 = __half22float2(h0), f1 = __half22float2(h1);
        return make_float4(f0.x, f0.y, f1.x, f1.y);
    }
    static __device__ __forceinline__ void st4(__half* p, float4 v) {
        *(__half2*)p       = __floats2half2_rn(v.x, v.y);
        *(__half2*)(p + 2) = __floats2half2_rn(v.z, v.w);
    }
    static __device__ __forceinline__ float ld1(const __half* p) { return __half2float(*p); }
};

// ---- packed f32x2 helpers (sm_103a) --------------------------------------
__device__ __forceinline__ unsigned long long pk2(float lo, float hi) {
    unsigned long long r;
    asm("mov.b64 %0, {%1, %2};" : "=l"(r) : "f"(lo), "f"(hi));
    return r;
}
__device__ __forceinline__ void fma2(unsigned long long& d,
                                     unsigned long long a,
                                     unsigned long long b) {
    asm("fma.rn.f32x2 %0, %1, %2, %0;" : "+l"(d) : "l"(a), "l"(b));
}
__device__ __forceinline__ float2 upk(unsigned long long v) {
    float2 f;
    asm("mov.b64 {%0, %1}, %2;" : "=f"(f.x), "=f"(f.y) : "l"(v));
    return f;
}

// ---------------------------------------------------------------------------
// Correlation: block = (h, di, b), 64 threads (48 active).
// Thread tile: 8 w x 10 dj, accumulators packed f32x2. Output fp16.
// ---------------------------------------------------------------------------
__global__ void __launch_bounds__(64, 6)
corr_kernel(const float* __restrict__ rgb,
            const float* __restrict__ dep,
            __half* __restrict__ out)
{
    const int h  = blockIdx.x;
    const int di = blockIdx.y;
    const int b  = blockIdx.z;
    const int tid = threadIdx.x;

    __shared__ __align__(16) float sm_rgb[16 * 192];
    __shared__ __align__(16) float sm_dep[16 * 212];   // sm_dep[x] = dep_row[x-10]

    const int wg  = tid % 24;            // w-tile of 8
    const int djg = tid / 24;            // 0..1 active
    const int w0  = wg * 8;
    const int dj0 = djg * 10;
    const int x0  = w0 + dj0;            // even
    const bool active = (tid < 48);

    const int hr = h + di - 10;
    if (hr < 0 || hr >= NH) {
        if (active) {
            uint4 z = {0u, 0u, 0u, 0u};
            #pragma unroll
            for (int j = 0; j < 10; j++) {
                size_t base = ((((size_t)b * NP + di) * NP + dj0 + j) * NH + h) * NW + w0;
                *(uint4*)&out[base] = z;    // 8 halfs = 16 B
            }
        }
        return;
    }

    unsigned long long acc2[10][4];
    #pragma unroll
    for (int j = 0; j < 10; j++)
        #pragma unroll
        for (int p = 0; p < 4; p++) acc2[j][p] = 0ull;

    const size_t bbase = (size_t)b * NC * NH * NW;

    #pragma unroll 1
    for (int cc = 0; cc < 4; cc++) {
        const int c0 = cc * 16;
        if (cc) __syncthreads();

        #pragma unroll
        for (int u = 0; u < 12; u++) {
            int i = tid + u * 64;
            int c = i / 48;
            int k4 = (i - c * 48) * 4;
            *(float4*)&sm_rgb[c * 192 + k4] =
                *(const float4*)&rgb[bbase + (size_t)(c0 + c) * (NH * NW) + h * NW + k4];
        }
        #pragma unroll
        for (int u = 0; u < 12; u++) {
            int i = tid + u * 64;
            int c = i / 48;
            int k4 = (i - c * 48) * 4;
            float4 v = *(const float4*)&dep[bbase + (size_t)(c0 + c) * (NH * NW) + hr * NW + k4];
            float* dst = &sm_dep[c * 212 + 10 + k4];
            *(float2*)(dst)     = make_float2(v.x, v.y);
            *(float2*)(dst + 2) = make_float2(v.z, v.w);
        }
        #pragma unroll
        for (int u = 0; u < 5; u++) {
            int i = tid + u * 64;
            int c = i / 20;
            int p = i - c * 20;
            int x = (p < 10) ? p : 192 + p;
            sm_dep[c * 212 + x] = 0.0f;
        }
        __syncthreads();

        if (!active) continue;

        #pragma unroll 2
        for (int c = 0; c < 16; c++) {
            const float* rp = &sm_rgb[c * 192 + w0];
            float4 ra = *(const float4*)rp;
            float4 rb = *(const float4*)(rp + 4);
            unsigned long long r2[4] = {
                pk2(ra.x, ra.y), pk2(ra.z, ra.w),
                pk2(rb.x, rb.y), pk2(rb.z, rb.w)
            };
            const float2* dpt = (const float2*)&sm_dep[c * 212 + x0];
            float2 dv2[9];
            #pragma unroll
            for (int k = 0; k < 9; k++) dv2[k] = dpt[k];

            #pragma unroll
            for (int j = 0; j < 10; j++) {
                if ((j & 1) == 0) {
                    #pragma unroll
                    for (int p = 0; p < 4; p++) {
                        unsigned long long d = pk2(dv2[p + j / 2].x, dv2[p + j / 2].y);
                        fma2(acc2[j][p], r2[p], d);
                    }
                } else {
                    #pragma unroll
                    for (int p = 0; p < 4; p++) {
                        unsigned long long d = pk2(dv2[p + (j - 1) / 2].y,
                                                   dv2[p + (j + 1) / 2].x);
                        fma2(acc2[j][p], r2[p], d);
                    }
                }
            }
        }
    }

    if (!active) return;
    #pragma unroll
    for (int j = 0; j < 10; j++) {
        float2 f0 = upk(acc2[j][0]);
        float2 f1 = upk(acc2[j][1]);
        float2 f2 = upk(acc2[j][2]);
        float2 f3 = upk(acc2[j][3]);
        size_t base = ((((size_t)b * NP + di) * NP + dj0 + j) * NH + h) * NW + w0;
        __half2 hh[4] = {
            __floats2half2_rn(f0.x, f0.y), __floats2half2_rn(f1.x, f1.y),
            __floats2half2_rn(f2.x, f2.y), __floats2half2_rn(f3.x, f3.y)
        };
        *(uint4*)&out[base] = *(uint4*)hh;
    }
}

// ---------------------------------------------------------------------------
// Depthwise 3x3x3, stride 1, pad 1, + leaky. Per-(n,c,d,htile) blocks.
// smem: 3 z-planes x 18 rows x (W+8), fp32.
// ---------------------------------------------------------------------------
template<int C, int D, int H, int W, int HT, typename Tin, typename Tout>
__global__ void dw_s1_kernel(const Tin* __restrict__ in,
                             const float* __restrict__ wgt,
                             const float* __restrict__ bias,
                             Tout* __restrict__ out)
{
    constexpr int SW = W + 8;
    __shared__ float smp[3 * 18 * SW];

    int bx = blockIdx.x;
    const int ht = bx % HT;  bx /= HT;
    const int d  = bx % D;   bx /= D;
    const int c  = bx % C;
    const int n  = bx / C;
    const int h0 = ht * 16;
    const int tid = threadIdx.x;

    const Tin* inb = in + (size_t)(n * C + c) * D * H * W;

    constexpr int WQ = W / 4;
    constexpr int nf4 = 54 * WQ;
    for (int i = tid; i < nf4; i += blockDim.x) {
        int row = i / WQ;
        int k4  = (i - row * WQ) * 4;
        int z = row / 18;
        int y = row - z * 18;
        int zi = d - 1 + z, yi = h0 - 1 + y;
        float4 v = {0.f, 0.f, 0.f, 0.f};
        if (zi >= 0 && zi < D && yi >= 0 && yi < H)
            v = VIO<Tin>::ld4(&inb[(size_t)zi * H * W + yi * W + k4]);
        *(float4*)&smp[row * SW + 4 + k4] = v;
    }
    for (int i = tid; i < 54 * 8; i += blockDim.x) {
        int row = i / 8;
        int p   = i - row * 8;
        int x   = (p < 4) ? p : W + p;
        smp[row * SW + x] = 0.0f;
    }

    float wt[27];
    #pragma unroll
    for (int k = 0; k < 27; k++) wt[k] = __ldg(&wgt[c * 27 + k]);
    const float bb = __ldg(&bias[c]);
    __syncthreads();

    constexpr int items = 16 * WQ;
    for (int it = tid; it < items; it += blockDim.x) {
        int hl  = it / WQ;
        int wg4 = (it - hl * WQ) * 4;
        float a0 = bb, a1 = bb, a2 = bb, a3 = bb;
        #pragma unroll
        for (int z = 0; z < 3; z++)
            #pragma unroll
            for (int y = 0; y < 3; y++) {
                const float* row = &smp[(z * 18 + hl + y) * SW];
                float m1  = row[wg4 + 3];
                float4 v4 = *(const float4*)&row[wg4 + 4];
                float p   = row[wg4 + 8];
                float w0 = wt[(z * 3 + y) * 3 + 0];
                float w1 = wt[(z * 3 + y) * 3 + 1];
                float w2 = wt[(z * 3 + y) * 3 + 2];
                a0 += w0 * m1   + w1 * v4.x + w2 * v4.y;
                a1 += w0 * v4.x + w1 * v4.y + w2 * v4.z;
                a2 += w0 * v4.y + w1 * v4.z + w2 * v4.w;
                a3 += w0 * v4.z + w1 * v4.w + w2 * p;
            }
        float4 o = {leaky(a0), leaky(a1), leaky(a2), leaky(a3)};
        VIO<Tout>::st4(&out[((size_t)(n * C + c) * D + d) * H * W + (h0 + hl) * W + wg4], o);
    }
}

// ---------------------------------------------------------------------------
// Depthwise 3x3x3, stride 2, pad 1, + leaky. Thread = 4 consecutive wo.
// ---------------------------------------------------------------------------
template<int C, int D, int H, int W, int Do, int Ho, int Wo, typename Tin, typename Tout>
__global__ void dw_s2_kernel(const Tin* __restrict__ in,
                             const float* __restrict__ wgt,
                             const float* __restrict__ bias,
                             Tout* __restrict__ out)
{
    constexpr int WQ = Wo / 4;
    constexpr int total = NB * C * Do * Ho * WQ;
    int idx = blockIdx.x * blockDim.x + threadIdx.x;
    if (idx >= total) return;
    int t = idx;
    const int q  = t % WQ; t /= WQ;
    const int ho = t % Ho; t /= Ho;
    const int dd = t % Do; t /= Do;
    const int c  = t % C;
    const int n  = t / C;
    const int g  = q * 8;

    const Tin* inb = in + (size_t)(n * C + c) * D * H * W;
    const float* wp  = &wgt[c * 27];
    const float bb = __ldg(&bias[c]);
    float a0 = bb, a1 = bb, a2 = bb, a3 = bb;

    #pragma unroll
    for (int kz = 0; kz < 3; kz++) {
        int zi = 2 * dd - 1 + kz;
        if (zi < 0 || zi >= D) continue;
        #pragma unroll
        for (int ky = 0; ky < 3; ky++) {
            int yi = 2 * ho - 1 + ky;
            if (yi < 0 || yi >= H) continue;
            const Tin* base = &inb[(size_t)zi * H * W + yi * W];
            float  m1 = (g > 0) ? VIO<Tin>::ld1(&base[g - 1]) : 0.0f;
            float4 v0 = VIO<Tin>::ld4(&base[g]);
            float4 v1 = VIO<Tin>::ld4(&base[g + 4]);
            float xv[9] = {m1, v0.x, v0.y, v0.z, v0.w, v1.x, v1.y, v1.z, v1.w};
            float w0 = __ldg(&wp[(kz * 3 + ky) * 3 + 0]);
            float w1 = __ldg(&wp[(kz * 3 + ky) * 3 + 1]);
            float w2 = __ldg(&wp[(kz * 3 + ky) * 3 + 2]);
            a0 += w0 * xv[0] + w1 * xv[1] + w2 * xv[2];
            a1 += w0 * xv[2] + w1 * xv[3] + w2 * xv[4];
            a2 += w0 * xv[4] + w1 * xv[5] + w2 * xv[6];
            a3 += w0 * xv[6] + w1 * xv[7] + w2 * xv[8];
        }
    }
    float4 o = {leaky(a0), leaky(a1), leaky(a2), leaky(a3)};
    size_t obase = ((((size_t)n * C + c) * Do + dd) * Ho + ho) * Wo + q * 4;
    VIO<Tout>::st4(&out[obase], o);
}

// ---------------------------------------------------------------------------
// Pointwise Cin->Cout + leaky. f32x2 accumulators, packed duplicated weights
// in smem (LDS.64 broadcast). Thread = 4 positions x COT co.
// ---------------------------------------------------------------------------
template<int Cin, int COT, typename Tin, typename Tout>
__global__ void pw_kernel(const Tin* __restrict__ in,
                          const float* __restrict__ wgt,
                          const float* __restrict__ bias,
                          Tout* __restrict__ out,
                          int Cout, int plane, int nquad)
{
    __shared__ unsigned long long sw2[COT * Cin];
    __shared__ float sb[COT];

    const int co0 = blockIdx.y * COT;
    const int tid = threadIdx.x;

    for (int i = tid; i < COT * Cin; i += blockDim.x) {
        int j  = i / Cin;
        int ci = i - j * Cin;
        float wv = wgt[(co0 + j) * Cin + ci];
        sw2[i] = pk2(wv, wv);
    }
    if (tid < COT) sb[tid] = bias[co0 + tid];
    __syncthreads();

    const int t = blockIdx.x * blockDim.x + tid;
    if (t >= nquad) return;
    const int s0 = t * 4;
    const int n  = s0 / plane;
    const int p  = s0 - n * plane;

    const Tin* inb = in + (size_t)n * Cin * plane + p;

    unsigned long long acc2[COT][2];
    #pragma unroll
    for (int j = 0; j < COT; j++) {
        float bv = sb[j];
        unsigned long long bp = pk2(bv, bv);
        acc2[j][0] = bp; acc2[j][1] = bp;
    }

    #pragma unroll
    for (int ci = 0; ci < Cin; ci++) {
        float4 x4 = VIO<Tin>::ld4(&inb[(size_t)ci * plane]);
        unsigned long long xa = pk2(x4.x, x4.y);
        unsigned long long xb = pk2(x4.z, x4.w);
        #pragma unroll
        for (int j = 0; j < COT; j++) {
            unsigned long long wv2 = sw2[j * Cin + ci];
            fma2(acc2[j][0], wv2, xa);
            fma2(acc2[j][1], wv2, xb);
        }
    }

    Tout* ob = out + (size_t)n * Cout * plane + p;
    #pragma unroll
    for (int j = 0; j < COT; j++) {
        float2 fa = upk(acc2[j][0]);
        float2 fb = upk(acc2[j][1]);
        float4 o = {leaky(fa.x), leaky(fa.y), leaky(fb.x), leaky(fb.y)};
        VIO<Tout>::st4(&ob[(size_t)(co0 + j) * plane], o);
    }
}

// ---------------------------------------------------------------------------
extern "C" void kernel_launch(void* const* d_in, const int* in_sizes, int n_in,
                              void* d_out, int out_size)
{
    const float* rgb   = (const float*)d_in[0];
    const float* dep   = (const float*)d_in[1];
    const float* dw1_w = (const float*)d_in[2];
    const float* dw1_b = (const float*)d_in[3];
    const float* pw1_w = (const float*)d_in[4];
    const float* pw1_b = (const float*)d_in[5];
    const float* dw2_w = (const float*)d_in[6];
    const float* dw2_b = (const float*)d_in[7];
    const float* pw2_w = (const float*)d_in[8];
    const float* pw2_b = (const float*)d_in[9];
    const float* dw3_w = (const float*)d_in[10];
    const float* dw3_b = (const float*)d_in[11];
    const float* pw3_w = (const float*)d_in[12];
    const float* pw3_b = (const float*)d_in[13];
    const float* dw4_w = (const float*)d_in[14];
    const float* dw4_b = (const float*)d_in[15];
    const float* pw4_w = (const float*)d_in[16];
    const float* pw4_b = (const float*)d_in[17];
    float* out = (float*)d_out;

    float *bufA = nullptr, *bufB = nullptr;
    cudaGetSymbolAddress((void**)&bufA, g_bufA);
    cudaGetSymbolAddress((void**)&bufB, g_bufB);
    __half* bufA_h = (__half*)bufA;
    __half* bufB_h = (__half*)bufB;

    // ---- correlation -> bufA (fp16) ----
    corr_kernel<<<dim3(NH, NP, NB), 64>>>(rgb, dep, bufA_h);

    // ---- block 1 (stride 1): dw 20ch (fp16->fp16), pw 20->20 (fp16->fp16) ----
    dw_s1_kernel<20, 20, 64, 192, 4, __half, __half>
        <<<NB * 20 * 20 * 4, 256>>>(bufA_h, dw1_w, dw1_b, bufB_h);
    {
        const int plane = 20 * 64 * 192;
        const int nquad = NB * plane / 4;
        pw_kernel<20, 20, __half, __half>
            <<<dim3((nquad + 255) / 256, 1), 256>>>(bufB_h, pw1_w, pw1_b, bufA_h,
                                                    20, plane, nquad);
    }

    // ---- block 2 (stride 2): dw (fp16->fp32) -> (20,10,32,96), pw 20->40 ----
    {
        const int threads = NB * 20 * 10 * 32 * (96 / 4);
        dw_s2_kernel<20, 20, 64, 192, 10, 32, 96, __half, float>
            <<<(threads + 255) / 256, 256>>>(bufA_h, dw2_w, dw2_b, bufB);
        const int plane = 10 * 32 * 96;
        const int nquad = NB * plane / 4;
        pw_kernel<20, 20, float, float>
            <<<dim3((nquad + 255) / 256, 2), 256>>>(bufB, pw2_w, pw2_b, bufA,
                                                    40, plane, nquad);
    }

    // ---- block 3 (stride 1): dw 40ch on (10,32,96), pw 40->40 (fp32) ----
    dw_s1_kernel<40, 10, 32, 96, 2, float, float>
        <<<NB * 40 * 10 * 2, 256>>>(bufA, dw3_w, dw3_b, bufB);
    {
        const int plane = 10 * 32 * 96;
        const int nquad = NB * plane / 4;
        pw_kernel<40, 20, float, float>
            <<<dim3((nquad + 255) / 256, 2), 256>>>(bufB, pw3_w, pw3_b, bufA,
                                                    40, plane, nquad);
    }

    // ---- block 4 (stride 2): dw -> (40,5,16,48), pw 40->80 -> d_out (fp32) ----
    {
        const int threads = NB * 40 * 5 * 16 * (48 / 4);
        dw_s2_kernel<40, 10, 32, 96, 5, 16, 48, float, float>
            <<<(threads + 255) / 256, 256>>>(bufA, dw4_w, dw4_b, bufB);
        const int plane = 5 * 16 * 48;
        const int nquad = NB * plane / 4;
        pw_kernel<40, 20, float, float>
            <<<dim3((nquad + 255) / 256, 4), 256>>>(bufB, pw4_w, pw4_b, out,
                                                    80, plane, nquad);
    }
}

// round 10
// speedup vs baseline: 1.1071x; 1.0183x over previous
#include <cuda_runtime.h>
#include <cuda_fp16.h>
#include <cstdint>

#define NB   8
#define NC   64
#define NH   64
#define NW   192
#define NP   20

__device__ float g_bufA[NB * NP * NP * NH * NW];
__device__ float g_bufB[NB * NP * NP * NH * NW];

__device__ __forceinline__ float leaky(float x) {
    return x > 0.0f ? x : 0.1f * x;
}

// ---- typed vector IO (fp32 or fp16 storage, fp32 compute) -----------------
template<typename T> struct VIO;
template<> struct VIO<float> {
    static __device__ __forceinline__ float4 ld4(const float* p) { return *(const float4*)p; }
    static __device__ __forceinline__ void st4(float* p, float4 v) { *(float4*)p = v; }
    static __device__ __forceinline__ float ld1(const float* p) { return *p; }
};
template<> struct VIO<__half> {
    static __device__ __forceinline__ float4 ld4(const __half* p) {
        __half2 h0 = *(const __half2*)p;
        __half2 h1 = *(const __half2*)(p + 2);
        float2 f0 = __half22float2(h0), f1 = __half22float2(h1);
        return make_float4(f0.x, f0.y, f1.x, f1.y);
    }
    static __device__ __forceinline__ void st4(__half* p, float4 v) {
        *(__half2*)p       = __floats2half2_rn(v.x, v.y);
        *(__half2*)(p + 2) = __floats2half2_rn(v.z, v.w);
    }
    static __device__ __forceinline__ float ld1(const __half* p) { return __half2float(*p); }
};

// ---- packed f32x2 helpers (sm_103a) --------------------------------------
__device__ __forceinline__ unsigned long long pk2(float lo, float hi) {
    unsigned long long r;
    asm("mov.b64 %0, {%1, %2};" : "=l"(r) : "f"(lo), "f"(hi));
    return r;
}
__device__ __forceinline__ void fma2(unsigned long long& d,
                                     unsigned long long a,
                                     unsigned long long b) {
    asm("fma.rn.f32x2 %0, %1, %2, %0;" : "+l"(d) : "l"(a), "l"(b));
}
__device__ __forceinline__ float2 upk(unsigned long long v) {
    float2 f;
    asm("mov.b64 {%0, %1}, %2;" : "=f"(f.x), "=f"(f.y) : "l"(v));
    return f;
}

// ---------------------------------------------------------------------------
// Correlation: block = (h, di-pair, b), 96 threads = 3 warps, ALL active.
// Thread: r = tid/48 selects di half; tile 8 w x 10 dj, f32x2 accumulators.
// Channels in 4 chunks of 16. smem = rgb 16*192 + dep 2*16*212 = 39.4 KB.
// Invalid depth rows -> zero planes -> outputs naturally zero.
// ---------------------------------------------------------------------------
__global__ void __launch_bounds__(96, 4)
corr_kernel(const float* __restrict__ rgb,
            const float* __restrict__ dep,
            __half* __restrict__ out)
{
    const int h  = blockIdx.x;
    const int dp = blockIdx.y;          // di = 2*dp + r
    const int b  = blockIdx.z;
    const int tid = threadIdx.x;

    __shared__ __align__(16) float sm_rgb[16 * 192];
    __shared__ __align__(16) float sm_dep[2 * 16 * 212];  // [r*16+c][x], x=w+dj

    const int r   = tid / 48;
    const int it  = tid % 48;
    const int wg  = it % 24;
    const int djg = it / 24;
    const int w0  = wg * 8;
    const int dj0 = djg * 10;
    const int x0  = w0 + dj0;           // even

    const int hr0 = h + 2 * dp - 10;
    const int hr1 = hr0 + 1;
    const bool v0 = (hr0 >= 0 && hr0 < NH);
    const bool v1 = (hr1 >= 0 && hr1 < NH);

    if (!v0 && !v1) {
        uint4 z = {0u, 0u, 0u, 0u};
        #pragma unroll
        for (int j = 0; j < 10; j++) {
            size_t base = ((((size_t)b * NP + 2 * dp + r) * NP + dj0 + j) * NH + h) * NW + w0;
            *(uint4*)&out[base] = z;
        }
        return;
    }

    unsigned long long acc2[10][4];
    #pragma unroll
    for (int j = 0; j < 10; j++)
        #pragma unroll
        for (int p = 0; p < 4; p++) acc2[j][p] = 0ull;

    const size_t bbase = (size_t)b * NC * NH * NW;

    #pragma unroll 1
    for (int cc = 0; cc < 4; cc++) {
        const int c0 = cc * 16;
        if (cc) __syncthreads();

        // rgb chunk: 768 float4, 8 per thread
        #pragma unroll
        for (int u = 0; u < 8; u++) {
            int i = tid + u * 96;
            int c = i / 48;
            int k4 = (i - c * 48) * 4;
            *(float4*)&sm_rgb[c * 192 + k4] =
                *(const float4*)&rgb[bbase + (size_t)(c0 + c) * (NH * NW) + h * NW + k4];
        }
        // dep interior: 2 rows x 16 ch x 48 float4 = 1536, 16 per thread
        #pragma unroll
        for (int u = 0; u < 16; u++) {
            int i = tid + u * 96;
            int rc = i / 48;                 // 0..31
            int k4 = (i - rc * 48) * 4;
            int rr = rc >> 4;
            int c  = rc & 15;
            int hr = rr ? hr1 : hr0;
            bool vr = rr ? v1 : v0;
            float4 v = {0.f, 0.f, 0.f, 0.f};
            if (vr)
                v = *(const float4*)&dep[bbase + (size_t)(c0 + c) * (NH * NW) + hr * NW + k4];
            float* dst = &sm_dep[rc * 212 + 10 + k4];
            *(float2*)(dst)     = make_float2(v.x, v.y);
            *(float2*)(dst + 2) = make_float2(v.z, v.w);
        }
        // dep edges: 2*16*20 = 640, ceil(640/96)=7 with guard
        #pragma unroll
        for (int u = 0; u < 7; u++) {
            int i = tid + u * 96;
            if (i < 640) {
                int rc = i / 20;
                int p = i - rc * 20;
                int x = (p < 10) ? p : 192 + p;
                sm_dep[rc * 212 + x] = 0.0f;
            }
        }
        __syncthreads();

        #pragma unroll 2
        for (int c = 0; c < 16; c++) {
            const float* rp = &sm_rgb[c * 192 + w0];
            float4 ra = *(const float4*)rp;
            float4 rb = *(const float4*)(rp + 4);
            unsigned long long r2[4] = {
                pk2(ra.x, ra.y), pk2(ra.z, ra.w),
                pk2(rb.x, rb.y), pk2(rb.z, rb.w)
            };
            const float2* dpt = (const float2*)&sm_dep[(r * 16 + c) * 212 + x0];
            float2 dv2[9];
            #pragma unroll
            for (int k = 0; k < 9; k++) dv2[k] = dpt[k];

            #pragma unroll
            for (int j = 0; j < 10; j++) {
                if ((j & 1) == 0) {
                    #pragma unroll
                    for (int p = 0; p < 4; p++) {
                        unsigned long long d = pk2(dv2[p + j / 2].x, dv2[p + j / 2].y);
                        fma2(acc2[j][p], r2[p], d);
                    }
                } else {
                    #pragma unroll
                    for (int p = 0; p < 4; p++) {
                        unsigned long long d = pk2(dv2[p + (j - 1) / 2].y,
                                                   dv2[p + (j + 1) / 2].x);
                        fma2(acc2[j][p], r2[p], d);
                    }
                }
            }
        }
    }

    #pragma unroll
    for (int j = 0; j < 10; j++) {
        float2 f0 = upk(acc2[j][0]);
        float2 f1 = upk(acc2[j][1]);
        float2 f2 = upk(acc2[j][2]);
        float2 f3 = upk(acc2[j][3]);
        size_t base = ((((size_t)b * NP + 2 * dp + r) * NP + dj0 + j) * NH + h) * NW + w0;
        __half2 hh[4] = {
            __floats2half2_rn(f0.x, f0.y), __floats2half2_rn(f1.x, f1.y),
            __floats2half2_rn(f2.x, f2.y), __floats2half2_rn(f3.x, f3.y)
        };
        *(uint4*)&out[base] = *(uint4*)hh;
    }
}

// ---------------------------------------------------------------------------
// Depthwise 3x3x3, stride 1, pad 1, + leaky. Per-(n,c,d,htile) blocks.
// smem: 3 z-planes x 18 rows x (W+8), fp32.
// ---------------------------------------------------------------------------
template<int C, int D, int H, int W, int HT, typename Tin, typename Tout>
__global__ void dw_s1_kernel(const Tin* __restrict__ in,
                             const float* __restrict__ wgt,
                             const float* __restrict__ bias,
                             Tout* __restrict__ out)
{
    constexpr int SW = W + 8;
    __shared__ float smp[3 * 18 * SW];

    int bx = blockIdx.x;
    const int ht = bx % HT;  bx /= HT;
    const int d  = bx % D;   bx /= D;
    const int c  = bx % C;
    const int n  = bx / C;
    const int h0 = ht * 16;
    const int tid = threadIdx.x;

    const Tin* inb = in + (size_t)(n * C + c) * D * H * W;

    constexpr int WQ = W / 4;
    constexpr int nf4 = 54 * WQ;
    for (int i = tid; i < nf4; i += blockDim.x) {
        int row = i / WQ;
        int k4  = (i - row * WQ) * 4;
        int z = row / 18;
        int y = row - z * 18;
        int zi = d - 1 + z, yi = h0 - 1 + y;
        float4 v = {0.f, 0.f, 0.f, 0.f};
        if (zi >= 0 && zi < D && yi >= 0 && yi < H)
            v = VIO<Tin>::ld4(&inb[(size_t)zi * H * W + yi * W + k4]);
        *(float4*)&smp[row * SW + 4 + k4] = v;
    }
    for (int i = tid; i < 54 * 8; i += blockDim.x) {
        int row = i / 8;
        int p   = i - row * 8;
        int x   = (p < 4) ? p : W + p;
        smp[row * SW + x] = 0.0f;
    }

    float wt[27];
    #pragma unroll
    for (int k = 0; k < 27; k++) wt[k] = __ldg(&wgt[c * 27 + k]);
    const float bb = __ldg(&bias[c]);
    __syncthreads();

    constexpr int items = 16 * WQ;
    for (int it = tid; it < items; it += blockDim.x) {
        int hl  = it / WQ;
        int wg4 = (it - hl * WQ) * 4;
        float a0 = bb, a1 = bb, a2 = bb, a3 = bb;
        #pragma unroll
        for (int z = 0; z < 3; z++)
            #pragma unroll
            for (int y = 0; y < 3; y++) {
                const float* row = &smp[(z * 18 + hl + y) * SW];
                float m1  = row[wg4 + 3];
                float4 v4 = *(const float4*)&row[wg4 + 4];
                float p   = row[wg4 + 8];
                float w0 = wt[(z * 3 + y) * 3 + 0];
                float w1 = wt[(z * 3 + y) * 3 + 1];
                float w2 = wt[(z * 3 + y) * 3 + 2];
                a0 += w0 * m1   + w1 * v4.x + w2 * v4.y;
                a1 += w0 * v4.x + w1 * v4.y + w2 * v4.z;
                a2 += w0 * v4.y + w1 * v4.z + w2 * v4.w;
                a3 += w0 * v4.z + w1 * v4.w + w2 * p;
            }
        float4 o = {leaky(a0), leaky(a1), leaky(a2), leaky(a3)};
        VIO<Tout>::st4(&out[((size_t)(n * C + c) * D + d) * H * W + (h0 + hl) * W + wg4], o);
    }
}

// ---------------------------------------------------------------------------
// Depthwise 3x3x3, stride 2, pad 1, + leaky. Thread = 4 consecutive wo.
// ---------------------------------------------------------------------------
template<int C, int D, int H, int W, int Do, int Ho, int Wo, typename Tin, typename Tout>
__global__ void dw_s2_kernel(const Tin* __restrict__ in,
                             const float* __restrict__ wgt,
                             const float* __restrict__ bias,
                             Tout* __restrict__ out)
{
    constexpr int WQ = Wo / 4;
    constexpr int total = NB * C * Do * Ho * WQ;
    int idx = blockIdx.x * blockDim.x + threadIdx.x;
    if (idx >= total) return;
    int t = idx;
    const int q  = t % WQ; t /= WQ;
    const int ho = t % Ho; t /= Ho;
    const int dd = t % Do; t /= Do;
    const int c  = t % C;
    const int n  = t / C;
    const int g  = q * 8;

    const Tin* inb = in + (size_t)(n * C + c) * D * H * W;
    const float* wp  = &wgt[c * 27];
    const float bb = __ldg(&bias[c]);
    float a0 = bb, a1 = bb, a2 = bb, a3 = bb;

    #pragma unroll
    for (int kz = 0; kz < 3; kz++) {
        int zi = 2 * dd - 1 + kz;
        if (zi < 0 || zi >= D) continue;
        #pragma unroll
        for (int ky = 0; ky < 3; ky++) {
            int yi = 2 * ho - 1 + ky;
            if (yi < 0 || yi >= H) continue;
            const Tin* base = &inb[(size_t)zi * H * W + yi * W];
            float  m1 = (g > 0) ? VIO<Tin>::ld1(&base[g - 1]) : 0.0f;
            float4 v0 = VIO<Tin>::ld4(&base[g]);
            float4 v1 = VIO<Tin>::ld4(&base[g + 4]);
            float xv[9] = {m1, v0.x, v0.y, v0.z, v0.w, v1.x, v1.y, v1.z, v1.w};
            float w0 = __ldg(&wp[(kz * 3 + ky) * 3 + 0]);
            float w1 = __ldg(&wp[(kz * 3 + ky) * 3 + 1]);
            float w2 = __ldg(&wp[(kz * 3 + ky) * 3 + 2]);
            a0 += w0 * xv[0] + w1 * xv[1] + w2 * xv[2];
            a1 += w0 * xv[2] + w1 * xv[3] + w2 * xv[4];
            a2 += w0 * xv[4] + w1 * xv[5] + w2 * xv[6];
            a3 += w0 * xv[6] + w1 * xv[7] + w2 * xv[8];
        }
    }
    float4 o = {leaky(a0), leaky(a1), leaky(a2), leaky(a3)};
    size_t obase = ((((size_t)n * C + c) * Do + dd) * Ho + ho) * Wo + q * 4;
    VIO<Tout>::st4(&out[obase], o);
}

// ---------------------------------------------------------------------------
// Pointwise Cin->Cout + leaky. f32x2 accumulators, packed duplicated weights
// in smem (LDS.64 broadcast). Thread = 4 positions x COT co.
// ---------------------------------------------------------------------------
template<int Cin, int COT, typename Tin, typename Tout>
__global__ void pw_kernel(const Tin* __restrict__ in,
                          const float* __restrict__ wgt,
                          const float* __restrict__ bias,
                          Tout* __restrict__ out,
                          int Cout, int plane, int nquad)
{
    __shared__ unsigned long long sw2[COT * Cin];
    __shared__ float sb[COT];

    const int co0 = blockIdx.y * COT;
    const int tid = threadIdx.x;

    for (int i = tid; i < COT * Cin; i += blockDim.x) {
        int j  = i / Cin;
        int ci = i - j * Cin;
        float wv = wgt[(co0 + j) * Cin + ci];
        sw2[i] = pk2(wv, wv);
    }
    if (tid < COT) sb[tid] = bias[co0 + tid];
    __syncthreads();

    const int t = blockIdx.x * blockDim.x + tid;
    if (t >= nquad) return;
    const int s0 = t * 4;
    const int n  = s0 / plane;
    const int p  = s0 - n * plane;

    const Tin* inb = in + (size_t)n * Cin * plane + p;

    unsigned long long acc2[COT][2];
    #pragma unroll
    for (int j = 0; j < COT; j++) {
        float bv = sb[j];
        unsigned long long bp = pk2(bv, bv);
        acc2[j][0] = bp; acc2[j][1] = bp;
    }

    #pragma unroll
    for (int ci = 0; ci < Cin; ci++) {
        float4 x4 = VIO<Tin>::ld4(&inb[(size_t)ci * plane]);
        unsigned long long xa = pk2(x4.x, x4.y);
        unsigned long long xb = pk2(x4.z, x4.w);
        #pragma unroll
        for (int j = 0; j < COT; j++) {
            unsigned long long wv2 = sw2[j * Cin + ci];
            fma2(acc2[j][0], wv2, xa);
            fma2(acc2[j][1], wv2, xb);
        }
    }

    Tout* ob = out + (size_t)n * Cout * plane + p;
    #pragma unroll
    for (int j = 0; j < COT; j++) {
        float2 fa = upk(acc2[j][0]);
        float2 fb = upk(acc2[j][1]);
        float4 o = {leaky(fa.x), leaky(fa.y), leaky(fb.x), leaky(fb.y)};
        VIO<Tout>::st4(&ob[(size_t)(co0 + j) * plane], o);
    }
}

// ---------------------------------------------------------------------------
extern "C" void kernel_launch(void* const* d_in, const int* in_sizes, int n_in,
                              void* d_out, int out_size)
{
    const float* rgb   = (const float*)d_in[0];
    const float* dep   = (const float*)d_in[1];
    const float* dw1_w = (const float*)d_in[2];
    const float* dw1_b = (const float*)d_in[3];
    const float* pw1_w = (const float*)d_in[4];
    const float* pw1_b = (const float*)d_in[5];
    const float* dw2_w = (const float*)d_in[6];
    const float* dw2_b = (const float*)d_in[7];
    const float* pw2_w = (const float*)d_in[8];
    const float* pw2_b = (const float*)d_in[9];
    const float* dw3_w = (const float*)d_in[10];
    const float* dw3_b = (const float*)d_in[11];
    const float* pw3_w = (const float*)d_in[12];
    const float* pw3_b = (const float*)d_in[13];
    const float* dw4_w = (const float*)d_in[14];
    const float* dw4_b = (const float*)d_in[15];
    const float* pw4_w = (const float*)d_in[16];
    const float* pw4_b = (const float*)d_in[17];
    float* out = (float*)d_out;

    float *bufA = nullptr, *bufB = nullptr;
    cudaGetSymbolAddress((void**)&bufA, g_bufA);
    cudaGetSymbolAddress((void**)&bufB, g_bufB);
    __half* bufA_h = (__half*)bufA;
    __half* bufB_h = (__half*)bufB;

    // ---- correlation -> bufA (fp16) ----
    corr_kernel<<<dim3(NH, NP / 2, NB), 96>>>(rgb, dep, bufA_h);

    // ---- block 1 (stride 1): dw 20ch (fp16->fp16), pw 20->20 (fp16->fp16) ----
    dw_s1_kernel<20, 20, 64, 192, 4, __half, __half>
        <<<NB * 20 * 20 * 4, 256>>>(bufA_h, dw1_w, dw1_b, bufB_h);
    {
        const int plane = 20 * 64 * 192;
        const int nquad = NB * plane / 4;
        pw_kernel<20, 20, __half, __half>
            <<<dim3((nquad + 255) / 256, 1), 256>>>(bufB_h, pw1_w, pw1_b, bufA_h,
                                                    20, plane, nquad);
    }

    // ---- block 2 (stride 2): dw (fp16->fp32) -> (20,10,32,96), pw 20->40 ----
    {
        const int threads = NB * 20 * 10 * 32 * (96 / 4);
        dw_s2_kernel<20, 20, 64, 192, 10, 32, 96, __half, float>
            <<<(threads + 255) / 256, 256>>>(bufA_h, dw2_w, dw2_b, bufB);
        const int plane = 10 * 32 * 96;
        const int nquad = NB * plane / 4;
        pw_kernel<20, 20, float, float>
            <<<dim3((nquad + 255) / 256, 2), 256>>>(bufB, pw2_w, pw2_b, bufA,
                                                    40, plane, nquad);
    }

    // ---- block 3 (stride 1): dw 40ch on (10,32,96), pw 40->40 (fp32) ----
    dw_s1_kernel<40, 10, 32, 96, 2, float, float>
        <<<NB * 40 * 10 * 2, 256>>>(bufA, dw3_w, dw3_b, bufB);
    {
        const int plane = 10 * 32 * 96;
        const int nquad = NB * plane / 4;
        pw_kernel<40, 20, float, float>
            <<<dim3((nquad + 255) / 256, 2), 256>>>(bufB, pw3_w, pw3_b, bufA,
                                                    40, plane, nquad);
    }

    // ---- block 4 (stride 2): dw -> (40,5,16,48), pw 40->80 -> d_out (fp32) ----
    {
        const int threads = NB * 40 * 5 * 16 * (48 / 4);
        dw_s2_kernel<40, 10, 32, 96, 5, 16, 48, float, float>
            <<<(threads + 255) / 256, 256>>>(bufA, dw4_w, dw4_b, bufB);
        const int plane = 5 * 16 * 48;
        const int nquad = NB * plane / 4;
        pw_kernel<40, 20, float, float>
            <<<dim3((nquad + 255) / 256, 4), 256>>>(bufB, pw4_w, pw4_b, out,
                                                    80, plane, nquad);
    }
}

// round 11
// speedup vs baseline: 1.1079x; 1.0008x over previous
#include <cuda_runtime.h>
#include <cuda_fp16.h>
#include <cstdint>

#define NB   8
#define NC   64
#define NH   64
#define NW   192
#define NP   20

__device__ float g_bufA[NB * NP * NP * NH * NW];
__device__ float g_bufB[NB * NP * NP * NH * NW];

__device__ __forceinline__ float leaky(float x) {
    return x > 0.0f ? x : 0.1f * x;
}

// ---- typed vector IO (fp32 or fp16 storage, fp32 compute) -----------------
template<typename T> struct VIO;
template<> struct VIO<float> {
    static __device__ __forceinline__ float4 ld4(const float* p) { return *(const float4*)p; }
    static __device__ __forceinline__ void st4(float* p, float4 v) { *(float4*)p = v; }
    static __device__ __forceinline__ float ld1(const float* p) { return *p; }
};
template<> struct VIO<__half> {
    // single 8-byte load: 4 halfs
    static __device__ __forceinline__ float4 ld4(const __half* p) {
        uint2 raw = *(const uint2*)p;                 // LDG.64
        __half2 h0 = *reinterpret_cast<__half2*>(&raw.x);
        __half2 h1 = *reinterpret_cast<__half2*>(&raw.y);
        float2 f0 = __half22float2(h0), f1 = __half22float2(h1);
        return make_float4(f0.x, f0.y, f1.x, f1.y);
    }
    // single 8-byte store: 4 halfs
    static __device__ __forceinline__ void st4(__half* p, float4 v) {
        __half2 h0 = __floats2half2_rn(v.x, v.y);
        __half2 h1 = __floats2half2_rn(v.z, v.w);
        uint2 raw;
        raw.x = *reinterpret_cast<uint32_t*>(&h0);
        raw.y = *reinterpret_cast<uint32_t*>(&h1);
        *(uint2*)p = raw;                             // STG.64
    }
    static __device__ __forceinline__ float ld1(const __half* p) { return __half2float(*p); }
};

// ---- packed f32x2 helpers (sm_103a) --------------------------------------
__device__ __forceinline__ unsigned long long pk2(float lo, float hi) {
    unsigned long long r;
    asm("mov.b64 %0, {%1, %2};" : "=l"(r) : "f"(lo), "f"(hi));
    return r;
}
__device__ __forceinline__ void fma2(unsigned long long& d,
                                     unsigned long long a,
                                     unsigned long long b) {
    asm("fma.rn.f32x2 %0, %1, %2, %0;" : "+l"(d) : "l"(a), "l"(b));
}
__device__ __forceinline__ float2 upk(unsigned long long v) {
    float2 f;
    asm("mov.b64 {%0, %1}, %2;" : "=f"(f.x), "=f"(f.y) : "l"(v));
    return f;
}

// ---------------------------------------------------------------------------
// Correlation: block = (h, di-pair, b), 96 threads = 3 warps, ALL active.
// Thread: r = tid/48 selects di half; tile 8 w x 10 dj, f32x2 accumulators.
// ---------------------------------------------------------------------------
__global__ void __launch_bounds__(96, 4)
corr_kernel(const float* __restrict__ rgb,
            const float* __restrict__ dep,
            __half* __restrict__ out)
{
    const int h  = blockIdx.x;
    const int dp = blockIdx.y;          // di = 2*dp + r
    const int b  = blockIdx.z;
    const int tid = threadIdx.x;

    __shared__ __align__(16) float sm_rgb[16 * 192];
    __shared__ __align__(16) float sm_dep[2 * 16 * 212];  // [r*16+c][x], x=w+dj

    const int r   = tid / 48;
    const int it  = tid % 48;
    const int wg  = it % 24;
    const int djg = it / 24;
    const int w0  = wg * 8;
    const int dj0 = djg * 10;
    const int x0  = w0 + dj0;           // even

    const int hr0 = h + 2 * dp - 10;
    const int hr1 = hr0 + 1;
    const bool v0 = (hr0 >= 0 && hr0 < NH);
    const bool v1 = (hr1 >= 0 && hr1 < NH);

    if (!v0 && !v1) {
        uint4 z = {0u, 0u, 0u, 0u};
        #pragma unroll
        for (int j = 0; j < 10; j++) {
            size_t base = ((((size_t)b * NP + 2 * dp + r) * NP + dj0 + j) * NH + h) * NW + w0;
            *(uint4*)&out[base] = z;
        }
        return;
    }

    unsigned long long acc2[10][4];
    #pragma unroll
    for (int j = 0; j < 10; j++)
        #pragma unroll
        for (int p = 0; p < 4; p++) acc2[j][p] = 0ull;

    const size_t bbase = (size_t)b * NC * NH * NW;

    #pragma unroll 1
    for (int cc = 0; cc < 4; cc++) {
        const int c0 = cc * 16;
        if (cc) __syncthreads();

        #pragma unroll
        for (int u = 0; u < 8; u++) {
            int i = tid + u * 96;
            int c = i / 48;
            int k4 = (i - c * 48) * 4;
            *(float4*)&sm_rgb[c * 192 + k4] =
                *(const float4*)&rgb[bbase + (size_t)(c0 + c) * (NH * NW) + h * NW + k4];
        }
        #pragma unroll
        for (int u = 0; u < 16; u++) {
            int i = tid + u * 96;
            int rc = i / 48;                 // 0..31
            int k4 = (i - rc * 48) * 4;
            int rr = rc >> 4;
            int c  = rc & 15;
            int hr = rr ? hr1 : hr0;
            bool vr = rr ? v1 : v0;
            float4 v = {0.f, 0.f, 0.f, 0.f};
            if (vr)
                v = *(const float4*)&dep[bbase + (size_t)(c0 + c) * (NH * NW) + hr * NW + k4];
            float* dst = &sm_dep[rc * 212 + 10 + k4];
            *(float2*)(dst)     = make_float2(v.x, v.y);
            *(float2*)(dst + 2) = make_float2(v.z, v.w);
        }
        #pragma unroll
        for (int u = 0; u < 7; u++) {
            int i = tid + u * 96;
            if (i < 640) {
                int rc = i / 20;
                int p = i - rc * 20;
                int x = (p < 10) ? p : 192 + p;
                sm_dep[rc * 212 + x] = 0.0f;
            }
        }
        __syncthreads();

        #pragma unroll 2
        for (int c = 0; c < 16; c++) {
            const float* rp = &sm_rgb[c * 192 + w0];
            float4 ra = *(const float4*)rp;
            float4 rb = *(const float4*)(rp + 4);
            unsigned long long r2[4] = {
                pk2(ra.x, ra.y), pk2(ra.z, ra.w),
                pk2(rb.x, rb.y), pk2(rb.z, rb.w)
            };
            const float2* dpt = (const float2*)&sm_dep[(r * 16 + c) * 212 + x0];
            float2 dv2[9];
            #pragma unroll
            for (int k = 0; k < 9; k++) dv2[k] = dpt[k];

            #pragma unroll
            for (int j = 0; j < 10; j++) {
                if ((j & 1) == 0) {
                    #pragma unroll
                    for (int p = 0; p < 4; p++) {
                        unsigned long long d = pk2(dv2[p + j / 2].x, dv2[p + j / 2].y);
                        fma2(acc2[j][p], r2[p], d);
                    }
                } else {
                    #pragma unroll
                    for (int p = 0; p < 4; p++) {
                        unsigned long long d = pk2(dv2[p + (j - 1) / 2].y,
                                                   dv2[p + (j + 1) / 2].x);
                        fma2(acc2[j][p], r2[p], d);
                    }
                }
            }
        }
    }

    #pragma unroll
    for (int j = 0; j < 10; j++) {
        float2 f0 = upk(acc2[j][0]);
        float2 f1 = upk(acc2[j][1]);
        float2 f2 = upk(acc2[j][2]);
        float2 f3 = upk(acc2[j][3]);
        size_t base = ((((size_t)b * NP + 2 * dp + r) * NP + dj0 + j) * NH + h) * NW + w0;
        __half2 hh[4] = {
            __floats2half2_rn(f0.x, f0.y), __floats2half2_rn(f1.x, f1.y),
            __floats2half2_rn(f2.x, f2.y), __floats2half2_rn(f3.x, f3.y)
        };
        *(uint4*)&out[base] = *(uint4*)hh;
    }
}

// ---------------------------------------------------------------------------
// Depthwise 3x3x3, stride 1, pad 1, + leaky. Per-(n,c,d,htile) blocks.
// ---------------------------------------------------------------------------
template<int C, int D, int H, int W, int HT, typename Tin, typename Tout>
__global__ void dw_s1_kernel(const Tin* __restrict__ in,
                             const float* __restrict__ wgt,
                             const float* __restrict__ bias,
                             Tout* __restrict__ out)
{
    constexpr int SW = W + 8;
    __shared__ float smp[3 * 18 * SW];

    int bx = blockIdx.x;
    const int ht = bx % HT;  bx /= HT;
    const int d  = bx % D;   bx /= D;
    const int c  = bx % C;
    const int n  = bx / C;
    const int h0 = ht * 16;
    const int tid = threadIdx.x;

    const Tin* inb = in + (size_t)(n * C + c) * D * H * W;

    constexpr int WQ = W / 4;
    constexpr int nf4 = 54 * WQ;
    for (int i = tid; i < nf4; i += blockDim.x) {
        int row = i / WQ;
        int k4  = (i - row * WQ) * 4;
        int z = row / 18;
        int y = row - z * 18;
        int zi = d - 1 + z, yi = h0 - 1 + y;
        float4 v = {0.f, 0.f, 0.f, 0.f};
        if (zi >= 0 && zi < D && yi >= 0 && yi < H)
            v = VIO<Tin>::ld4(&inb[(size_t)zi * H * W + yi * W + k4]);
        *(float4*)&smp[row * SW + 4 + k4] = v;
    }
    for (int i = tid; i < 54 * 8; i += blockDim.x) {
        int row = i / 8;
        int p   = i - row * 8;
        int x   = (p < 4) ? p : W + p;
        smp[row * SW + x] = 0.0f;
    }

    float wt[27];
    #pragma unroll
    for (int k = 0; k < 27; k++) wt[k] = __ldg(&wgt[c * 27 + k]);
    const float bb = __ldg(&bias[c]);
    __syncthreads();

    constexpr int items = 16 * WQ;
    for (int it = tid; it < items; it += blockDim.x) {
        int hl  = it / WQ;
        int wg4 = (it - hl * WQ) * 4;
        float a0 = bb, a1 = bb, a2 = bb, a3 = bb;
        #pragma unroll
        for (int z = 0; z < 3; z++)
            #pragma unroll
            for (int y = 0; y < 3; y++) {
                const float* row = &smp[(z * 18 + hl + y) * SW];
                float m1  = row[wg4 + 3];
                float4 v4 = *(const float4*)&row[wg4 + 4];
                float p   = row[wg4 + 8];
                float w0 = wt[(z * 3 + y) * 3 + 0];
                float w1 = wt[(z * 3 + y) * 3 + 1];
                float w2 = wt[(z * 3 + y) * 3 + 2];
                a0 += w0 * m1   + w1 * v4.x + w2 * v4.y;
                a1 += w0 * v4.x + w1 * v4.y + w2 * v4.z;
                a2 += w0 * v4.y + w1 * v4.z + w2 * v4.w;
                a3 += w0 * v4.z + w1 * v4.w + w2 * p;
            }
        float4 o = {leaky(a0), leaky(a1), leaky(a2), leaky(a3)};
        VIO<Tout>::st4(&out[((size_t)(n * C + c) * D + d) * H * W + (h0 + hl) * W + wg4], o);
    }
}

// ---------------------------------------------------------------------------
// Depthwise 3x3x3, stride 2, pad 1, + leaky. Thread = 8 consecutive wo.
// Per (kz,ky) row: 1 scalar + 4x vec4 loads cover 17 inputs for 8 outputs.
// ---------------------------------------------------------------------------
template<int C, int D, int H, int W, int Do, int Ho, int Wo, typename Tin, typename Tout>
__global__ void dw_s2_kernel(const Tin* __restrict__ in,
                             const float* __restrict__ wgt,
                             const float* __restrict__ bias,
                             Tout* __restrict__ out)
{
    constexpr int WO8 = Wo / 8;
    constexpr int total = NB * C * Do * Ho * WO8;
    int idx = blockIdx.x * blockDim.x + threadIdx.x;
    if (idx >= total) return;
    int t = idx;
    const int q  = t % WO8; t /= WO8;
    const int ho = t % Ho; t /= Ho;
    const int dd = t % Do; t /= Do;
    const int c  = t % C;
    const int n  = t / C;
    const int g  = q * 16;               // input x base (= 2*wo0)

    const Tin* inb = in + (size_t)(n * C + c) * D * H * W;
    const float* wp  = &wgt[c * 27];
    const float bb = __ldg(&bias[c]);
    float a[8];
    #pragma unroll
    for (int k = 0; k < 8; k++) a[k] = bb;

    #pragma unroll
    for (int kz = 0; kz < 3; kz++) {
        int zi = 2 * dd - 1 + kz;
        if (zi < 0 || zi >= D) continue;
        #pragma unroll
        for (int ky = 0; ky < 3; ky++) {
            int yi = 2 * ho - 1 + ky;
            if (yi < 0 || yi >= H) continue;
            const Tin* base = &inb[(size_t)zi * H * W + yi * W];
            float m1 = (g > 0) ? VIO<Tin>::ld1(&base[g - 1]) : 0.0f;
            float4 v0 = VIO<Tin>::ld4(&base[g]);
            float4 v1 = VIO<Tin>::ld4(&base[g + 4]);
            float4 v2 = VIO<Tin>::ld4(&base[g + 8]);
            float4 v3 = VIO<Tin>::ld4(&base[g + 12]);
            float xv[17] = {m1,
                            v0.x, v0.y, v0.z, v0.w,
                            v1.x, v1.y, v1.z, v1.w,
                            v2.x, v2.y, v2.z, v2.w,
                            v3.x, v3.y, v3.z, v3.w};
            float w0 = __ldg(&wp[(kz * 3 + ky) * 3 + 0]);
            float w1 = __ldg(&wp[(kz * 3 + ky) * 3 + 1]);
            float w2 = __ldg(&wp[(kz * 3 + ky) * 3 + 2]);
            #pragma unroll
            for (int k = 0; k < 8; k++)
                a[k] += w0 * xv[2 * k] + w1 * xv[2 * k + 1] + w2 * xv[2 * k + 2];
        }
    }
    size_t obase = ((((size_t)n * C + c) * Do + dd) * Ho + ho) * Wo + q * 8;
    float4 o0 = {leaky(a[0]), leaky(a[1]), leaky(a[2]), leaky(a[3])};
    float4 o1 = {leaky(a[4]), leaky(a[5]), leaky(a[6]), leaky(a[7])};
    VIO<Tout>::st4(&out[obase], o0);
    VIO<Tout>::st4(&out[obase + 4], o1);
}

// ---------------------------------------------------------------------------
// Pointwise Cin->Cout + leaky. f32x2 accumulators, packed duplicated weights.
// ---------------------------------------------------------------------------
template<int Cin, int COT, typename Tin, typename Tout>
__global__ void pw_kernel(const Tin* __restrict__ in,
                          const float* __restrict__ wgt,
                          const float* __restrict__ bias,
                          Tout* __restrict__ out,
                          int Cout, int plane, int nquad)
{
    __shared__ unsigned long long sw2[COT * Cin];
    __shared__ float sb[COT];

    const int co0 = blockIdx.y * COT;
    const int tid = threadIdx.x;

    for (int i = tid; i < COT * Cin; i += blockDim.x) {
        int j  = i / Cin;
        int ci = i - j * Cin;
        float wv = wgt[(co0 + j) * Cin + ci];
        sw2[i] = pk2(wv, wv);
    }
    if (tid < COT) sb[tid] = bias[co0 + tid];
    __syncthreads();

    const int t = blockIdx.x * blockDim.x + tid;
    if (t >= nquad) return;
    const int s0 = t * 4;
    const int n  = s0 / plane;
    const int p  = s0 - n * plane;

    const Tin* inb = in + (size_t)n * Cin * plane + p;

    unsigned long long acc2[COT][2];
    #pragma unroll
    for (int j = 0; j < COT; j++) {
        float bv = sb[j];
        unsigned long long bp = pk2(bv, bv);
        acc2[j][0] = bp; acc2[j][1] = bp;
    }

    #pragma unroll
    for (int ci = 0; ci < Cin; ci++) {
        float4 x4 = VIO<Tin>::ld4(&inb[(size_t)ci * plane]);
        unsigned long long xa = pk2(x4.x, x4.y);
        unsigned long long xb = pk2(x4.z, x4.w);
        #pragma unroll
        for (int j = 0; j < COT; j++) {
            unsigned long long wv2 = sw2[j * Cin + ci];
            fma2(acc2[j][0], wv2, xa);
            fma2(acc2[j][1], wv2, xb);
        }
    }

    Tout* ob = out + (size_t)n * Cout * plane + p;
    #pragma unroll
    for (int j = 0; j < COT; j++) {
        float2 fa = upk(acc2[j][0]);
        float2 fb = upk(acc2[j][1]);
        float4 o = {leaky(fa.x), leaky(fa.y), leaky(fb.x), leaky(fb.y)};
        VIO<Tout>::st4(&ob[(size_t)(co0 + j) * plane], o);
    }
}

// ---------------------------------------------------------------------------
extern "C" void kernel_launch(void* const* d_in, const int* in_sizes, int n_in,
                              void* d_out, int out_size)
{
    const float* rgb   = (const float*)d_in[0];
    const float* dep   = (const float*)d_in[1];
    const float* dw1_w = (const float*)d_in[2];
    const float* dw1_b = (const float*)d_in[3];
    const float* pw1_w = (const float*)d_in[4];
    const float* pw1_b = (const float*)d_in[5];
    const float* dw2_w = (const float*)d_in[6];
    const float* dw2_b = (const float*)d_in[7];
    const float* pw2_w = (const float*)d_in[8];
    const float* pw2_b = (const float*)d_in[9];
    const float* dw3_w = (const float*)d_in[10];
    const float* dw3_b = (const float*)d_in[11];
    const float* pw3_w = (const float*)d_in[12];
    const float* pw3_b = (const float*)d_in[13];
    const float* dw4_w = (const float*)d_in[14];
    const float* dw4_b = (const float*)d_in[15];
    const float* pw4_w = (const float*)d_in[16];
    const float* pw4_b = (const float*)d_in[17];
    float* out = (float*)d_out;

    float *bufA = nullptr, *bufB = nullptr;
    cudaGetSymbolAddress((void**)&bufA, g_bufA);
    cudaGetSymbolAddress((void**)&bufB, g_bufB);
    __half* bufA_h = (__half*)bufA;
    __half* bufB_h = (__half*)bufB;

    // ---- correlation -> bufA (fp16) ----
    corr_kernel<<<dim3(NH, NP / 2, NB), 96>>>(rgb, dep, bufA_h);

    // ---- block 1 (stride 1): dw 20ch (fp16->fp16), pw 20->20 (fp16->fp16) ----
    dw_s1_kernel<20, 20, 64, 192, 4, __half, __half>
        <<<NB * 20 * 20 * 4, 256>>>(bufA_h, dw1_w, dw1_b, bufB_h);
    {
        const int plane = 20 * 64 * 192;
        const int nquad = NB * plane / 4;
        pw_kernel<20, 20, __half, __half>
            <<<dim3((nquad + 255) / 256, 1), 256>>>(bufB_h, pw1_w, pw1_b, bufA_h,
                                                    20, plane, nquad);
    }

    // ---- block 2 (stride 2): dw (fp16->fp32) -> (20,10,32,96), pw 20->40 ----
    {
        const int threads = NB * 20 * 10 * 32 * (96 / 8);
        dw_s2_kernel<20, 20, 64, 192, 10, 32, 96, __half, float>
            <<<(threads + 255) / 256, 256>>>(bufA_h, dw2_w, dw2_b, bufB);
        const int plane = 10 * 32 * 96;
        const int nquad = NB * plane / 4;
        pw_kernel<20, 20, float, float>
            <<<dim3((nquad + 255) / 256, 2), 256>>>(bufB, pw2_w, pw2_b, bufA,
                                                    40, plane, nquad);
    }

    // ---- block 3 (stride 1): dw 40ch on (10,32,96), pw 40->40 (fp32) ----
    dw_s1_kernel<40, 10, 32, 96, 2, float, float>
        <<<NB * 40 * 10 * 2, 256>>>(bufA, dw3_w, dw3_b, bufB);
    {
        const int plane = 10 * 32 * 96;
        const int nquad = NB * plane / 4;
        pw_kernel<40, 20, float, float>
            <<<dim3((nquad + 255) / 256, 2), 256>>>(bufB, pw3_w, pw3_b, bufA,
                                                    40, plane, nquad);
    }

    // ---- block 4 (stride 2): dw -> (40,5,16,48), pw 40->80 -> d_out (fp32) ----
    {
        const int threads = NB * 40 * 5 * 16 * (48 / 8);
        dw_s2_kernel<40, 10, 32, 96, 5, 16, 48, float, float>
            <<<(threads + 255) / 256, 256>>>(bufA, dw4_w, dw4_b, bufB);
        const int plane = 5 * 16 * 48;
        const int nquad = NB * plane / 4;
        pw_kernel<40, 20, float, float>
            <<<dim3((nquad + 255) / 256, 4), 256>>>(bufB, pw4_w, pw4_b, out,
                                                    80, plane, nquad);
    }
}

// round 12
// speedup vs baseline: 1.1171x; 1.0082x over previous
#include <cuda_runtime.h>
#include <cuda_fp16.h>
#include <cstdint>

#define NB   8
#define NC   64
#define NH   64
#define NW   192
#define NP   20

__device__ float g_bufA[NB * NP * NP * NH * NW];
__device__ float g_bufB[NB * NP * NP * NH * NW];

__device__ __forceinline__ float leaky(float x) {
    return x > 0.0f ? x : 0.1f * x;
}

// ---- typed vector IO (fp32 or fp16 storage, fp32 compute) -----------------
template<typename T> struct VIO;
template<> struct VIO<float> {
    static __device__ __forceinline__ float4 ld4(const float* p) { return *(const float4*)p; }
    static __device__ __forceinline__ void st4(float* p, float4 v) { *(float4*)p = v; }
    static __device__ __forceinline__ float ld1(const float* p) { return *p; }
};
template<> struct VIO<__half> {
    static __device__ __forceinline__ float4 ld4(const __half* p) {
        uint2 raw = *(const uint2*)p;                 // LDG.64
        __half2 h0 = *reinterpret_cast<__half2*>(&raw.x);
        __half2 h1 = *reinterpret_cast<__half2*>(&raw.y);
        float2 f0 = __half22float2(h0), f1 = __half22float2(h1);
        return make_float4(f0.x, f0.y, f1.x, f1.y);
    }
    static __device__ __forceinline__ void st4(__half* p, float4 v) {
        __half2 h0 = __floats2half2_rn(v.x, v.y);
        __half2 h1 = __floats2half2_rn(v.z, v.w);
        uint2 raw;
        raw.x = *reinterpret_cast<uint32_t*>(&h0);
        raw.y = *reinterpret_cast<uint32_t*>(&h1);
        *(uint2*)p = raw;                             // STG.64
    }
    static __device__ __forceinline__ float ld1(const __half* p) { return __half2float(*p); }
};

// ---- packed f32x2 helpers (sm_103a) --------------------------------------
__device__ __forceinline__ unsigned long long pk2(float lo, float hi) {
    unsigned long long r;
    asm("mov.b64 %0, {%1, %2};" : "=l"(r) : "f"(lo), "f"(hi));
    return r;
}
__device__ __forceinline__ void fma2(unsigned long long& d,
                                     unsigned long long a,
                                     unsigned long long b) {
    asm("fma.rn.f32x2 %0, %1, %2, %0;" : "+l"(d) : "l"(a), "l"(b));
}
__device__ __forceinline__ float2 upk(unsigned long long v) {
    float2 f;
    asm("mov.b64 {%0, %1}, %2;" : "=f"(f.x), "=f"(f.y) : "l"(v));
    return f;
}

// ---------------------------------------------------------------------------
// Correlation: block = (h, di-pair, b), 96 threads = 3 warps, ALL active.
// ---------------------------------------------------------------------------
__global__ void __launch_bounds__(96, 4)
corr_kernel(const float* __restrict__ rgb,
            const float* __restrict__ dep,
            __half* __restrict__ out)
{
    const int h  = blockIdx.x;
    const int dp = blockIdx.y;          // di = 2*dp + r
    const int b  = blockIdx.z;
    const int tid = threadIdx.x;

    __shared__ __align__(16) float sm_rgb[16 * 192];
    __shared__ __align__(16) float sm_dep[2 * 16 * 212];  // [r*16+c][x], x=w+dj

    const int r   = tid / 48;
    const int it  = tid % 48;
    const int wg  = it % 24;
    const int djg = it / 24;
    const int w0  = wg * 8;
    const int dj0 = djg * 10;
    const int x0  = w0 + dj0;           // even

    const int hr0 = h + 2 * dp - 10;
    const int hr1 = hr0 + 1;
    const bool v0 = (hr0 >= 0 && hr0 < NH);
    const bool v1 = (hr1 >= 0 && hr1 < NH);

    if (!v0 && !v1) {
        uint4 z = {0u, 0u, 0u, 0u};
        #pragma unroll
        for (int j = 0; j < 10; j++) {
            size_t base = ((((size_t)b * NP + 2 * dp + r) * NP + dj0 + j) * NH + h) * NW + w0;
            *(uint4*)&out[base] = z;
        }
        return;
    }

    unsigned long long acc2[10][4];
    #pragma unroll
    for (int j = 0; j < 10; j++)
        #pragma unroll
        for (int p = 0; p < 4; p++) acc2[j][p] = 0ull;

    const size_t bbase = (size_t)b * NC * NH * NW;

    #pragma unroll 1
    for (int cc = 0; cc < 4; cc++) {
        const int c0 = cc * 16;
        if (cc) __syncthreads();

        #pragma unroll
        for (int u = 0; u < 8; u++) {
            int i = tid + u * 96;
            int c = i / 48;
            int k4 = (i - c * 48) * 4;
            *(float4*)&sm_rgb[c * 192 + k4] =
                *(const float4*)&rgb[bbase + (size_t)(c0 + c) * (NH * NW) + h * NW + k4];
        }
        #pragma unroll
        for (int u = 0; u < 16; u++) {
            int i = tid + u * 96;
            int rc = i / 48;                 // 0..31
            int k4 = (i - rc * 48) * 4;
            int rr = rc >> 4;
            int c  = rc & 15;
            int hr = rr ? hr1 : hr0;
            bool vr = rr ? v1 : v0;
            float4 v = {0.f, 0.f, 0.f, 0.f};
            if (vr)
                v = *(const float4*)&dep[bbase + (size_t)(c0 + c) * (NH * NW) + hr * NW + k4];
            float* dst = &sm_dep[rc * 212 + 10 + k4];
            *(float2*)(dst)     = make_float2(v.x, v.y);
            *(float2*)(dst + 2) = make_float2(v.z, v.w);
        }
        #pragma unroll
        for (int u = 0; u < 7; u++) {
            int i = tid + u * 96;
            if (i < 640) {
                int rc = i / 20;
                int p = i - rc * 20;
                int x = (p < 10) ? p : 192 + p;
                sm_dep[rc * 212 + x] = 0.0f;
            }
        }
        __syncthreads();

        #pragma unroll 2
        for (int c = 0; c < 16; c++) {
            const float* rp = &sm_rgb[c * 192 + w0];
            float4 ra = *(const float4*)rp;
            float4 rb = *(const float4*)(rp + 4);
            unsigned long long r2[4] = {
                pk2(ra.x, ra.y), pk2(ra.z, ra.w),
                pk2(rb.x, rb.y), pk2(rb.z, rb.w)
            };
            const float2* dpt = (const float2*)&sm_dep[(r * 16 + c) * 212 + x0];
            float2 dv2[9];
            #pragma unroll
            for (int k = 0; k < 9; k++) dv2[k] = dpt[k];

            #pragma unroll
            for (int j = 0; j < 10; j++) {
                if ((j & 1) == 0) {
                    #pragma unroll
                    for (int p = 0; p < 4; p++) {
                        unsigned long long d = pk2(dv2[p + j / 2].x, dv2[p + j / 2].y);
                        fma2(acc2[j][p], r2[p], d);
                    }
                } else {
                    #pragma unroll
                    for (int p = 0; p < 4; p++) {
                        unsigned long long d = pk2(dv2[p + (j - 1) / 2].y,
                                                   dv2[p + (j + 1) / 2].x);
                        fma2(acc2[j][p], r2[p], d);
                    }
                }
            }
        }
    }

    #pragma unroll
    for (int j = 0; j < 10; j++) {
        float2 f0 = upk(acc2[j][0]);
        float2 f1 = upk(acc2[j][1]);
        float2 f2 = upk(acc2[j][2]);
        float2 f3 = upk(acc2[j][3]);
        size_t base = ((((size_t)b * NP + 2 * dp + r) * NP + dj0 + j) * NH + h) * NW + w0;
        __half2 hh[4] = {
            __floats2half2_rn(f0.x, f0.y), __floats2half2_rn(f1.x, f1.y),
            __floats2half2_rn(f2.x, f2.y), __floats2half2_rn(f3.x, f3.y)
        };
        *(uint4*)&out[base] = *(uint4*)hh;
    }
}

// ---------------------------------------------------------------------------
// Depthwise 3x3x3, stride 1, pad 1, + leaky. Per-(n,c,d,htile) blocks.
// Compute uses packed f32x2: per (z,y) row 6 FFMA2 + 5 packs vs 12 FFMA.
// Duplicated weight pairs held in registers (27 x u64).
// ---------------------------------------------------------------------------
template<int C, int D, int H, int W, int HT, typename Tin, typename Tout>
__global__ void __launch_bounds__(256)
dw_s1_kernel(const Tin* __restrict__ in,
             const float* __restrict__ wgt,
             const float* __restrict__ bias,
             Tout* __restrict__ out)
{
    constexpr int SW = W + 8;
    __shared__ float smp[3 * 18 * SW];

    int bx = blockIdx.x;
    const int ht = bx % HT;  bx /= HT;
    const int d  = bx % D;   bx /= D;
    const int c  = bx % C;
    const int n  = bx / C;
    const int h0 = ht * 16;
    const int tid = threadIdx.x;

    const Tin* inb = in + (size_t)(n * C + c) * D * H * W;

    constexpr int WQ = W / 4;
    constexpr int nf4 = 54 * WQ;
    for (int i = tid; i < nf4; i += blockDim.x) {
        int row = i / WQ;
        int k4  = (i - row * WQ) * 4;
        int z = row / 18;
        int y = row - z * 18;
        int zi = d - 1 + z, yi = h0 - 1 + y;
        float4 v = {0.f, 0.f, 0.f, 0.f};
        if (zi >= 0 && zi < D && yi >= 0 && yi < H)
            v = VIO<Tin>::ld4(&inb[(size_t)zi * H * W + yi * W + k4]);
        *(float4*)&smp[row * SW + 4 + k4] = v;
    }
    for (int i = tid; i < 54 * 8; i += blockDim.x) {
        int row = i / 8;
        int p   = i - row * 8;
        int x   = (p < 4) ? p : W + p;
        smp[row * SW + x] = 0.0f;
    }

    // duplicated weight pairs in registers
    unsigned long long wt2[27];
    #pragma unroll
    for (int k = 0; k < 27; k++) {
        float wv = __ldg(&wgt[c * 27 + k]);
        wt2[k] = pk2(wv, wv);
    }
    const float bb = __ldg(&bias[c]);
    const unsigned long long bb2 = pk2(bb, bb);
    __syncthreads();

    constexpr int items = 16 * WQ;
    for (int it = tid; it < items; it += blockDim.x) {
        int hl  = it / WQ;
        int wg4 = (it - hl * WQ) * 4;
        unsigned long long A01 = bb2, A23 = bb2;
        #pragma unroll
        for (int z = 0; z < 3; z++)
            #pragma unroll
            for (int y = 0; y < 3; y++) {
                const float* row = &smp[(z * 18 + hl + y) * SW];
                float m1  = row[wg4 + 3];
                float4 v4 = *(const float4*)&row[wg4 + 4];
                float pr  = row[wg4 + 8];
                unsigned long long d0 = pk2(m1,   v4.x);
                unsigned long long d1 = pk2(v4.x, v4.y);
                unsigned long long d2 = pk2(v4.y, v4.z);
                unsigned long long d3 = pk2(v4.z, v4.w);
                unsigned long long d4 = pk2(v4.w, pr);
                const int kb = (z * 3 + y) * 3;
                fma2(A01, wt2[kb + 0], d0);
                fma2(A01, wt2[kb + 1], d1);
                fma2(A01, wt2[kb + 2], d2);
                fma2(A23, wt2[kb + 0], d2);
                fma2(A23, wt2[kb + 1], d3);
                fma2(A23, wt2[kb + 2], d4);
            }
        float2 f01 = upk(A01);
        float2 f23 = upk(A23);
        float4 o = {leaky(f01.x), leaky(f01.y), leaky(f23.x), leaky(f23.y)};
        VIO<Tout>::st4(&out[((size_t)(n * C + c) * D + d) * H * W + (h0 + hl) * W + wg4], o);
    }
}

// ---------------------------------------------------------------------------
// Depthwise 3x3x3, stride 2, pad 1, + leaky. Thread = 8 consecutive wo.
// ---------------------------------------------------------------------------
template<int C, int D, int H, int W, int Do, int Ho, int Wo, typename Tin, typename Tout>
__global__ void dw_s2_kernel(const Tin* __restrict__ in,
                             const float* __restrict__ wgt,
                             const float* __restrict__ bias,
                             Tout* __restrict__ out)
{
    constexpr int WO8 = Wo / 8;
    constexpr int total = NB * C * Do * Ho * WO8;
    int idx = blockIdx.x * blockDim.x + threadIdx.x;
    if (idx >= total) return;
    int t = idx;
    const int q  = t % WO8; t /= WO8;
    const int ho = t % Ho; t /= Ho;
    const int dd = t % Do; t /= Do;
    const int c  = t % C;
    const int n  = t / C;
    const int g  = q * 16;               // input x base (= 2*wo0)

    const Tin* inb = in + (size_t)(n * C + c) * D * H * W;
    const float* wp  = &wgt[c * 27];
    const float bb = __ldg(&bias[c]);
    float a[8];
    #pragma unroll
    for (int k = 0; k < 8; k++) a[k] = bb;

    #pragma unroll
    for (int kz = 0; kz < 3; kz++) {
        int zi = 2 * dd - 1 + kz;
        if (zi < 0 || zi >= D) continue;
        #pragma unroll
        for (int ky = 0; ky < 3; ky++) {
            int yi = 2 * ho - 1 + ky;
            if (yi < 0 || yi >= H) continue;
            const Tin* base = &inb[(size_t)zi * H * W + yi * W];
            float m1 = (g > 0) ? VIO<Tin>::ld1(&base[g - 1]) : 0.0f;
            float4 v0 = VIO<Tin>::ld4(&base[g]);
            float4 v1 = VIO<Tin>::ld4(&base[g + 4]);
            float4 v2 = VIO<Tin>::ld4(&base[g + 8]);
            float4 v3 = VIO<Tin>::ld4(&base[g + 12]);
            float xv[17] = {m1,
                            v0.x, v0.y, v0.z, v0.w,
                            v1.x, v1.y, v1.z, v1.w,
                            v2.x, v2.y, v2.z, v2.w,
                            v3.x, v3.y, v3.z, v3.w};
            float w0 = __ldg(&wp[(kz * 3 + ky) * 3 + 0]);
            float w1 = __ldg(&wp[(kz * 3 + ky) * 3 + 1]);
            float w2 = __ldg(&wp[(kz * 3 + ky) * 3 + 2]);
            #pragma unroll
            for (int k = 0; k < 8; k++)
                a[k] += w0 * xv[2 * k] + w1 * xv[2 * k + 1] + w2 * xv[2 * k + 2];
        }
    }
    size_t obase = ((((size_t)n * C + c) * Do + dd) * Ho + ho) * Wo + q * 8;
    float4 o0 = {leaky(a[0]), leaky(a[1]), leaky(a[2]), leaky(a[3])};
    float4 o1 = {leaky(a[4]), leaky(a[5]), leaky(a[6]), leaky(a[7])};
    VIO<Tout>::st4(&out[obase], o0);
    VIO<Tout>::st4(&out[obase + 4], o1);
}

// ---------------------------------------------------------------------------
// Pointwise Cin->Cout + leaky. f32x2 accumulators, packed duplicated weights.
// ---------------------------------------------------------------------------
template<int Cin, int COT, typename Tin, typename Tout>
__global__ void pw_kernel(const Tin* __restrict__ in,
                          const float* __restrict__ wgt,
                          const float* __restrict__ bias,
                          Tout* __restrict__ out,
                          int Cout, int plane, int nquad)
{
    __shared__ unsigned long long sw2[COT * Cin];
    __shared__ float sb[COT];

    const int co0 = blockIdx.y * COT;
    const int tid = threadIdx.x;

    for (int i = tid; i < COT * Cin; i += blockDim.x) {
        int j  = i / Cin;
        int ci = i - j * Cin;
        float wv = wgt[(co0 + j) * Cin + ci];
        sw2[i] = pk2(wv, wv);
    }
    if (tid < COT) sb[tid] = bias[co0 + tid];
    __syncthreads();

    const int t = blockIdx.x * blockDim.x + tid;
    if (t >= nquad) return;
    const int s0 = t * 4;
    const int n  = s0 / plane;
    const int p  = s0 - n * plane;

    const Tin* inb = in + (size_t)n * Cin * plane + p;

    unsigned long long acc2[COT][2];
    #pragma unroll
    for (int j = 0; j < COT; j++) {
        float bv = sb[j];
        unsigned long long bp = pk2(bv, bv);
        acc2[j][0] = bp; acc2[j][1] = bp;
    }

    #pragma unroll
    for (int ci = 0; ci < Cin; ci++) {
        float4 x4 = VIO<Tin>::ld4(&inb[(size_t)ci * plane]);
        unsigned long long xa = pk2(x4.x, x4.y);
        unsigned long long xb = pk2(x4.z, x4.w);
        #pragma unroll
        for (int j = 0; j < COT; j++) {
            unsigned long long wv2 = sw2[j * Cin + ci];
            fma2(acc2[j][0], wv2, xa);
            fma2(acc2[j][1], wv2, xb);
        }
    }

    Tout* ob = out + (size_t)n * Cout * plane + p;
    #pragma unroll
    for (int j = 0; j < COT; j++) {
        float2 fa = upk(acc2[j][0]);
        float2 fb = upk(acc2[j][1]);
        float4 o = {leaky(fa.x), leaky(fa.y), leaky(fb.x), leaky(fb.y)};
        VIO<Tout>::st4(&ob[(size_t)(co0 + j) * plane], o);
    }
}

// ---------------------------------------------------------------------------
extern "C" void kernel_launch(void* const* d_in, const int* in_sizes, int n_in,
                              void* d_out, int out_size)
{
    const float* rgb   = (const float*)d_in[0];
    const float* dep   = (const float*)d_in[1];
    const float* dw1_w = (const float*)d_in[2];
    const float* dw1_b = (const float*)d_in[3];
    const float* pw1_w = (const float*)d_in[4];
    const float* pw1_b = (const float*)d_in[5];
    const float* dw2_w = (const float*)d_in[6];
    const float* dw2_b = (const float*)d_in[7];
    const float* pw2_w = (const float*)d_in[8];
    const float* pw2_b = (const float*)d_in[9];
    const float* dw3_w = (const float*)d_in[10];
    const float* dw3_b = (const float*)d_in[11];
    const float* pw3_w = (const float*)d_in[12];
    const float* pw3_b = (const float*)d_in[13];
    const float* dw4_w = (const float*)d_in[14];
    const float* dw4_b = (const float*)d_in[15];
    const float* pw4_w = (const float*)d_in[16];
    const float* pw4_b = (const float*)d_in[17];
    float* out = (float*)d_out;

    float *bufA = nullptr, *bufB = nullptr;
    cudaGetSymbolAddress((void**)&bufA, g_bufA);
    cudaGetSymbolAddress((void**)&bufB, g_bufB);
    __half* bufA_h = (__half*)bufA;
    __half* bufB_h = (__half*)bufB;

    // ---- correlation -> bufA (fp16) ----
    corr_kernel<<<dim3(NH, NP / 2, NB), 96>>>(rgb, dep, bufA_h);

    // ---- block 1 (stride 1): dw 20ch (fp16->fp16), pw 20->20 (fp16->fp16) ----
    dw_s1_kernel<20, 20, 64, 192, 4, __half, __half>
        <<<NB * 20 * 20 * 4, 256>>>(bufA_h, dw1_w, dw1_b, bufB_h);
    {
        const int plane = 20 * 64 * 192;
        const int nquad = NB * plane / 4;
        pw_kernel<20, 20, __half, __half>
            <<<dim3((nquad + 255) / 256, 1), 256>>>(bufB_h, pw1_w, pw1_b, bufA_h,
                                                    20, plane, nquad);
    }

    // ---- block 2 (stride 2): dw (fp16->fp32) -> (20,10,32,96), pw 20->40 ----
    {
        const int threads = NB * 20 * 10 * 32 * (96 / 8);
        dw_s2_kernel<20, 20, 64, 192, 10, 32, 96, __half, float>
            <<<(threads + 255) / 256, 256>>>(bufA_h, dw2_w, dw2_b, bufB);
        const int plane = 10 * 32 * 96;
        const int nquad = NB * plane / 4;
        pw_kernel<20, 20, float, float>
            <<<dim3((nquad + 255) / 256, 2), 256>>>(bufB, pw2_w, pw2_b, bufA,
                                                    40, plane, nquad);
    }

    // ---- block 3 (stride 1): dw 40ch on (10,32,96), pw 40->40 (fp32) ----
    dw_s1_kernel<40, 10, 32, 96, 2, float, float>
        <<<NB * 40 * 10 * 2, 256>>>(bufA, dw3_w, dw3_b, bufB);
    {
        const int plane = 10 * 32 * 96;
        const int nquad = NB * plane / 4;
        pw_kernel<40, 20, float, float>
            <<<dim3((nquad + 255) / 256, 2), 256>>>(bufB, pw3_w, pw3_b, bufA,
                                                    40, plane, nquad);
    }

    // ---- block 4 (stride 2): dw -> (40,5,16,48), pw 40->80 -> d_out (fp32) ----
    {
        const int threads = NB * 40 * 5 * 16 * (48 / 8);
        dw_s2_kernel<40, 10, 32, 96, 5, 16, 48, float, float>
            <<<(threads + 255) / 256, 256>>>(bufA, dw4_w, dw4_b, bufB);
        const int plane = 5 * 16 * 48;
        const int nquad = NB * plane / 4;
        pw_kernel<40, 20, float, float>
            <<<dim3((nquad + 255) / 256, 4), 256>>>(bufB, pw4_w, pw4_b, out,
                                                    80, plane, nquad);
    }
}

// round 14
// speedup vs baseline: 1.1176x; 1.0005x over previous
#include <cuda_runtime.h>
#include <cuda_fp16.h>
#include <cstdint>

#define NB   8
#define NC   64
#define NH   64
#define NW   192
#define NP   20

__device__ float g_bufA[NB * NP * NP * NH * NW];
__device__ float g_bufB[NB * NP * NP * NH * NW];

__device__ __forceinline__ float leaky(float x) {
    return x > 0.0f ? x : 0.1f * x;
}

// ---- typed vector IO (fp32 or fp16 storage, fp32 compute) -----------------
template<typename T> struct VIO;
template<> struct VIO<float> {
    static __device__ __forceinline__ float4 ld4(const float* p) { return *(const float4*)p; }
    static __device__ __forceinline__ void st4(float* p, float4 v) { *(float4*)p = v; }
    static __device__ __forceinline__ float ld1(const float* p) { return *p; }
};
template<> struct VIO<__half> {
    static __device__ __forceinline__ float4 ld4(const __half* p) {
        uint2 raw = *(const uint2*)p;                 // LDG.64
        __half2 h0 = *reinterpret_cast<__half2*>(&raw.x);
        __half2 h1 = *reinterpret_cast<__half2*>(&raw.y);
        float2 f0 = __half22float2(h0), f1 = __half22float2(h1);
        return make_float4(f0.x, f0.y, f1.x, f1.y);
    }
    static __device__ __forceinline__ void st4(__half* p, float4 v) {
        __half2 h0 = __floats2half2_rn(v.x, v.y);
        __half2 h1 = __floats2half2_rn(v.z, v.w);
        uint2 raw;
        raw.x = *reinterpret_cast<uint32_t*>(&h0);
        raw.y = *reinterpret_cast<uint32_t*>(&h1);
        *(uint2*)p = raw;                             // STG.64
    }
    static __device__ __forceinline__ float ld1(const __half* p) { return __half2float(*p); }
};

// ---- packed f32x2 helpers (sm_103a) --------------------------------------
__device__ __forceinline__ unsigned long long pk2(float lo, float hi) {
    unsigned long long r;
    asm("mov.b64 %0, {%1, %2};" : "=l"(r) : "f"(lo), "f"(hi));
    return r;
}
__device__ __forceinline__ void fma2(unsigned long long& d,
                                     unsigned long long a,
                                     unsigned long long b) {
    asm("fma.rn.f32x2 %0, %1, %2, %0;" : "+l"(d) : "l"(a), "l"(b));
}
__device__ __forceinline__ float2 upk(unsigned long long v) {
    float2 f;
    asm("mov.b64 {%0, %1}, %2;" : "=f"(f.x), "=f"(f.y) : "l"(v));
    return f;
}

// ---------------------------------------------------------------------------
// Correlation: block = (h, di-pair, b), 96 threads = 3 warps, ALL active.
// Inner loop: depth window + rgb pairs loaded as aligned u64 (LDS.64);
// even-dj operands need ZERO packs, odd-dj 4 packs each.
// ---------------------------------------------------------------------------
__global__ void __launch_bounds__(96, 4)
corr_kernel(const float* __restrict__ rgb,
            const float* __restrict__ dep,
            __half* __restrict__ out)
{
    const int h  = blockIdx.x;
    const int dp = blockIdx.y;          // di = 2*dp + r
    const int b  = blockIdx.z;
    const int tid = threadIdx.x;

    __shared__ __align__(16) float sm_rgb[16 * 192];
    __shared__ __align__(16) float sm_dep[2 * 16 * 212];  // [r*16+c][x], x=w+dj

    const int r   = tid / 48;
    const int it  = tid % 48;
    const int wg  = it % 24;
    const int djg = it / 24;
    const int w0  = wg * 8;
    const int dj0 = djg * 10;
    const int x0  = w0 + dj0;           // even

    const int hr0 = h + 2 * dp - 10;
    const int hr1 = hr0 + 1;
    const bool v0 = (hr0 >= 0 && hr0 < NH);
    const bool v1 = (hr1 >= 0 && hr1 < NH);

    if (!v0 && !v1) {
        uint4 z = {0u, 0u, 0u, 0u};
        #pragma unroll
        for (int j = 0; j < 10; j++) {
            size_t base = ((((size_t)b * NP + 2 * dp + r) * NP + dj0 + j) * NH + h) * NW + w0;
            *(uint4*)&out[base] = z;
        }
        return;
    }

    unsigned long long acc2[10][4];
    #pragma unroll
    for (int j = 0; j < 10; j++)
        #pragma unroll
        for (int p = 0; p < 4; p++) acc2[j][p] = 0ull;

    const size_t bbase = (size_t)b * NC * NH * NW;

    #pragma unroll 1
    for (int cc = 0; cc < 4; cc++) {
        const int c0 = cc * 16;
        if (cc) __syncthreads();

        #pragma unroll
        for (int u = 0; u < 8; u++) {
            int i = tid + u * 96;
            int c = i / 48;
            int k4 = (i - c * 48) * 4;
            *(float4*)&sm_rgb[c * 192 + k4] =
                *(const float4*)&rgb[bbase + (size_t)(c0 + c) * (NH * NW) + h * NW + k4];
        }
        #pragma unroll
        for (int u = 0; u < 16; u++) {
            int i = tid + u * 96;
            int rc = i / 48;                 // 0..31
            int k4 = (i - rc * 48) * 4;
            int rr = rc >> 4;
            int c  = rc & 15;
            int hr = rr ? hr1 : hr0;
            bool vr = rr ? v1 : v0;
            float4 v = {0.f, 0.f, 0.f, 0.f};
            if (vr)
                v = *(const float4*)&dep[bbase + (size_t)(c0 + c) * (NH * NW) + hr * NW + k4];
            float* dst = &sm_dep[rc * 212 + 10 + k4];
            *(float2*)(dst)     = make_float2(v.x, v.y);
            *(float2*)(dst + 2) = make_float2(v.z, v.w);
        }
        #pragma unroll
        for (int u = 0; u < 7; u++) {
            int i = tid + u * 96;
            if (i < 640) {
                int rc = i / 20;
                int p = i - rc * 20;
                int x = (p < 10) ? p : 192 + p;
                sm_dep[rc * 212 + x] = 0.0f;
            }
        }
        __syncthreads();

        #pragma unroll 2
        for (int c = 0; c < 16; c++) {
            // rgb pairs: 4 aligned u64 loads, no packs
            const unsigned long long* rpu =
                (const unsigned long long*)&sm_rgb[c * 192 + w0];
            unsigned long long r2[4];
            #pragma unroll
            for (int p = 0; p < 4; p++) r2[p] = rpu[p];

            // depth window: 9 aligned u64 loads (x0 even), no packs
            const unsigned long long* dpt =
                (const unsigned long long*)&sm_dep[(r * 16 + c) * 212 + x0];
            unsigned long long dvu[9];
            float2 dvf[9];
            #pragma unroll
            for (int k = 0; k < 9; k++) {
                dvu[k] = dpt[k];
                dvf[k] = upk(dvu[k]);     // register-level aliasing
            }

            #pragma unroll
            for (int m = 0; m < 5; m++) {
                // even j = 2m: operand is dvu directly
                #pragma unroll
                for (int p = 0; p < 4; p++)
                    fma2(acc2[2 * m][p], r2[p], dvu[p + m]);
                // odd j = 2m+1: cross-pair (hi of k, lo of k+1)
                #pragma unroll
                for (int p = 0; p < 4; p++) {
                    unsigned long long d = pk2(dvf[p + m].y, dvf[p + m + 1].x);
                    fma2(acc2[2 * m + 1][p], r2[p], d);
                }
            }
        }
    }

    #pragma unroll
    for (int j = 0; j < 10; j++) {
        float2 f0 = upk(acc2[j][0]);
        float2 f1 = upk(acc2[j][1]);
        float2 f2 = upk(acc2[j][2]);
        float2 f3 = upk(acc2[j][3]);
        size_t base = ((((size_t)b * NP + 2 * dp + r) * NP + dj0 + j) * NH + h) * NW + w0;
        __half2 hh[4] = {
            __floats2half2_rn(f0.x, f0.y), __floats2half2_rn(f1.x, f1.y),
            __floats2half2_rn(f2.x, f2.y), __floats2half2_rn(f3.x, f3.y)
        };
        *(uint4*)&out[base] = *(uint4*)hh;
    }
}

// ---------------------------------------------------------------------------
// Depthwise 3x3x3, stride 1, pad 1, + leaky. Per-(n,c,d,htile) blocks.
// Packed f32x2 compute, duplicated weight pairs in registers.
// ---------------------------------------------------------------------------
template<int C, int D, int H, int W, int HT, typename Tin, typename Tout>
__global__ void __launch_bounds__(256)
dw_s1_kernel(const Tin* __restrict__ in,
             const float* __restrict__ wgt,
             const float* __restrict__ bias,
             Tout* __restrict__ out)
{
    constexpr int SW = W + 8;
    __shared__ float smp[3 * 18 * SW];

    int bx = blockIdx.x;
    const int ht = bx % HT;  bx /= HT;
    const int d  = bx % D;   bx /= D;
    const int c  = bx % C;
    const int n  = bx / C;
    const int h0 = ht * 16;
    const int tid = threadIdx.x;

    const Tin* inb = in + (size_t)(n * C + c) * D * H * W;

    constexpr int WQ = W / 4;
    constexpr int nf4 = 54 * WQ;
    for (int i = tid; i < nf4; i += blockDim.x) {
        int row = i / WQ;
        int k4  = (i - row * WQ) * 4;
        int z = row / 18;
        int y = row - z * 18;
        int zi = d - 1 + z, yi = h0 - 1 + y;
        float4 v = {0.f, 0.f, 0.f, 0.f};
        if (zi >= 0 && zi < D && yi >= 0 && yi < H)
            v = VIO<Tin>::ld4(&inb[(size_t)zi * H * W + yi * W + k4]);
        *(float4*)&smp[row * SW + 4 + k4] = v;
    }
    for (int i = tid; i < 54 * 8; i += blockDim.x) {
        int row = i / 8;
        int p   = i - row * 8;
        int x   = (p < 4) ? p : W + p;
        smp[row * SW + x] = 0.0f;
    }

    unsigned long long wt2[27];
    #pragma unroll
    for (int k = 0; k < 27; k++) {
        float wv = __ldg(&wgt[c * 27 + k]);
        wt2[k] = pk2(wv, wv);
    }
    const float bb = __ldg(&bias[c]);
    const unsigned long long bb2 = pk2(bb, bb);
    __syncthreads();

    constexpr int items = 16 * WQ;
    for (int it = tid; it < items; it += blockDim.x) {
        int hl  = it / WQ;
        int wg4 = (it - hl * WQ) * 4;
        unsigned long long A01 = bb2, A23 = bb2;
        #pragma unroll
        for (int z = 0; z < 3; z++)
            #pragma unroll
            for (int y = 0; y < 3; y++) {
                const float* row = &smp[(z * 18 + hl + y) * SW];
                float m1  = row[wg4 + 3];
                float4 v4 = *(const float4*)&row[wg4 + 4];
                float pr  = row[wg4 + 8];
                unsigned long long d0 = pk2(m1,   v4.x);
                unsigned long long d1 = pk2(v4.x, v4.y);
                unsigned long long d2 = pk2(v4.y, v4.z);
                unsigned long long d3 = pk2(v4.z, v4.w);
                unsigned long long d4 = pk2(v4.w, pr);
                const int kb = (z * 3 + y) * 3;
                fma2(A01, wt2[kb + 0], d0);
                fma2(A01, wt2[kb + 1], d1);
                fma2(A01, wt2[kb + 2], d2);
                fma2(A23, wt2[kb + 0], d2);
                fma2(A23, wt2[kb + 1], d3);
                fma2(A23, wt2[kb + 2], d4);
            }
        float2 f01 = upk(A01);
        float2 f23 = upk(A23);
        float4 o = {leaky(f01.x), leaky(f01.y), leaky(f23.x), leaky(f23.y)};
        VIO<Tout>::st4(&out[((size_t)(n * C + c) * D + d) * H * W + (h0 + hl) * W + wg4], o);
    }
}

// ---------------------------------------------------------------------------
// Depthwise 3x3x3, stride 2, pad 1, + leaky. Thread = 8 consecutive wo.
// ---------------------------------------------------------------------------
template<int C, int D, int H, int W, int Do, int Ho, int Wo, typename Tin, typename Tout>
__global__ void dw_s2_kernel(const Tin* __restrict__ in,
                             const float* __restrict__ wgt,
                             const float* __restrict__ bias,
                             Tout* __restrict__ out)
{
    constexpr int WO8 = Wo / 8;
    constexpr int total = NB * C * Do * Ho * WO8;
    int idx = blockIdx.x * blockDim.x + threadIdx.x;
    if (idx >= total) return;
    int t = idx;
    const int q  = t % WO8; t /= WO8;
    const int ho = t % Ho; t /= Ho;
    const int dd = t % Do; t /= Do;
    const int c  = t % C;
    const int n  = t / C;
    const int g  = q * 16;               // input x base (= 2*wo0)

    const Tin* inb = in + (size_t)(n * C + c) * D * H * W;
    const float* wp  = &wgt[c * 27];
    const float bb = __ldg(&bias[c]);
    float a[8];
    #pragma unroll
    for (int k = 0; k < 8; k++) a[k] = bb;

    #pragma unroll
    for (int kz = 0; kz < 3; kz++) {
        int zi = 2 * dd - 1 + kz;
        if (zi < 0 || zi >= D) continue;
        #pragma unroll
        for (int ky = 0; ky < 3; ky++) {
            int yi = 2 * ho - 1 + ky;
            if (yi < 0 || yi >= H) continue;
            const Tin* base = &inb[(size_t)zi * H * W + yi * W];
            float m1 = (g > 0) ? VIO<Tin>::ld1(&base[g - 1]) : 0.0f;
            float4 v0 = VIO<Tin>::ld4(&base[g]);
            float4 v1 = VIO<Tin>::ld4(&base[g + 4]);
            float4 v2 = VIO<Tin>::ld4(&base[g + 8]);
            float4 v3 = VIO<Tin>::ld4(&base[g + 12]);
            float xv[17] = {m1,
                            v0.x, v0.y, v0.z, v0.w,
                            v1.x, v1.y, v1.z, v1.w,
                            v2.x, v2.y, v2.z, v2.w,
                            v3.x, v3.y, v3.z, v3.w};
            float w0 = __ldg(&wp[(kz * 3 + ky) * 3 + 0]);
            float w1 = __ldg(&wp[(kz * 3 + ky) * 3 + 1]);
            float w2 = __ldg(&wp[(kz * 3 + ky) * 3 + 2]);
            #pragma unroll
            for (int k = 0; k < 8; k++)
                a[k] += w0 * xv[2 * k] + w1 * xv[2 * k + 1] + w2 * xv[2 * k + 2];
        }
    }
    size_t obase = ((((size_t)n * C + c) * Do + dd) * Ho + ho) * Wo + q * 8;
    float4 o0 = {leaky(a[0]), leaky(a[1]), leaky(a[2]), leaky(a[3])};
    float4 o1 = {leaky(a[4]), leaky(a[5]), leaky(a[6]), leaky(a[7])};
    VIO<Tout>::st4(&out[obase], o0);
    VIO<Tout>::st4(&out[obase + 4], o1);
}

// ---------------------------------------------------------------------------
// Pointwise Cin->Cout + leaky. f32x2 accumulators, packed duplicated weights.
// ---------------------------------------------------------------------------
template<int Cin, int COT, typename Tin, typename Tout>
__global__ void pw_kernel(const Tin* __restrict__ in,
                          const float* __restrict__ wgt,
                          const float* __restrict__ bias,
                          Tout* __restrict__ out,
                          int Cout, int plane, int nquad)
{
    __shared__ unsigned long long sw2[COT * Cin];
    __shared__ float sb[COT];

    const int co0 = blockIdx.y * COT;
    const int tid = threadIdx.x;

    for (int i = tid; i < COT * Cin; i += blockDim.x) {
        int j  = i / Cin;
        int ci = i - j * Cin;
        float wv = wgt[(co0 + j) * Cin + ci];
        sw2[i] = pk2(wv, wv);
    }
    if (tid < COT) sb[tid] = bias[co0 + tid];
    __syncthreads();

    const int t = blockIdx.x * blockDim.x + tid;
    if (t >= nquad) return;
    const int s0 = t * 4;
    const int n  = s0 / plane;
    const int p  = s0 - n * plane;

    const Tin* inb = in + (size_t)n * Cin * plane + p;

    unsigned long long acc2[COT][2];
    #pragma unroll
    for (int j = 0; j < COT; j++) {
        float bv = sb[j];
        unsigned long long bp = pk2(bv, bv);
        acc2[j][0] = bp; acc2[j][1] = bp;
    }

    #pragma unroll
    for (int ci = 0; ci < Cin; ci++) {
        float4 x4 = VIO<Tin>::ld4(&inb[(size_t)ci * plane]);
        unsigned long long xa = pk2(x4.x, x4.y);
        unsigned long long xb = pk2(x4.z, x4.w);
        #pragma unroll
        for (int j = 0; j < COT; j++) {
            unsigned long long wv2 = sw2[j * Cin + ci];
            fma2(acc2[j][0], wv2, xa);
            fma2(acc2[j][1], wv2, xb);
        }
    }

    Tout* ob = out + (size_t)n * Cout * plane + p;
    #pragma unroll
    for (int j = 0; j < COT; j++) {
        float2 fa = upk(acc2[j][0]);
        float2 fb = upk(acc2[j][1]);
        float4 o = {leaky(fa.x), leaky(fa.y), leaky(fb.x), leaky(fb.y)};
        VIO<Tout>::st4(&ob[(size_t)(co0 + j) * plane], o);
    }
}

// ---------------------------------------------------------------------------
extern "C" void kernel_launch(void* const* d_in, const int* in_sizes, int n_in,
                              void* d_out, int out_size)
{
    const float* rgb   = (const float*)d_in[0];
    const float* dep   = (const float*)d_in[1];
    const float* dw1_w = (const float*)d_in[2];
    const float* dw1_b = (const float*)d_in[3];
    const float* pw1_w = (const float*)d_in[4];
    const float* pw1_b = (const float*)d_in[5];
    const float* dw2_w = (const float*)d_in[6];
    const float* dw2_b = (const float*)d_in[7];
    const float* pw2_w = (const float*)d_in[8];
    const float* pw2_b = (const float*)d_in[9];
    const float* dw3_w = (const float*)d_in[10];
    const float* dw3_b = (const float*)d_in[11];
    const float* pw3_w = (const float*)d_in[12];
    const float* pw3_b = (const float*)d_in[13];
    const float* dw4_w = (const float*)d_in[14];
    const float* dw4_b = (const float*)d_in[15];
    const float* pw4_w = (const float*)d_in[16];
    const float* pw4_b = (const float*)d_in[17];
    float* out = (float*)d_out;

    float *bufA = nullptr, *bufB = nullptr;
    cudaGetSymbolAddress((void**)&bufA, g_bufA);
    cudaGetSymbolAddress((void**)&bufB, g_bufB);
    __half* bufA_h = (__half*)bufA;
    __half* bufB_h = (__half*)bufB;

    // ---- correlation -> bufA (fp16) ----
    corr_kernel<<<dim3(NH, NP / 2, NB), 96>>>(rgb, dep, bufA_h);

    // ---- block 1 (stride 1): dw 20ch (fp16->fp16), pw 20->20 (fp16->fp16) ----
    dw_s1_kernel<20, 20, 64, 192, 4, __half, __half>
        <<<NB * 20 * 20 * 4, 256>>>(bufA_h, dw1_w, dw1_b, bufB_h);
    {
        const int plane = 20 * 64 * 192;
        const int nquad = NB * plane / 4;
        pw_kernel<20, 20, __half, __half>
            <<<dim3((nquad + 255) / 256, 1), 256>>>(bufB_h, pw1_w, pw1_b, bufA_h,
                                                    20, plane, nquad);
    }

    // ---- block 2 (stride 2): dw (fp16->fp32) -> (20,10,32,96), pw 20->40 ----
    {
        const int threads = NB * 20 * 10 * 32 * (96 / 8);
        dw_s2_kernel<20, 20, 64, 192, 10, 32, 96, __half, float>
            <<<(threads + 255) / 256, 256>>>(bufA_h, dw2_w, dw2_b, bufB);
        const int plane = 10 * 32 * 96;
        const int nquad = NB * plane / 4;
        pw_kernel<20, 20, float, float>
            <<<dim3((nquad + 255) / 256, 2), 256>>>(bufB, pw2_w, pw2_b, bufA,
                                                    40, plane, nquad);
    }

    // ---- block 3 (stride 1): dw 40ch on (10,32,96), pw 40->40 (fp32) ----
    dw_s1_kernel<40, 10, 32, 96, 2, float, float>
        <<<NB * 40 * 10 * 2, 256>>>(bufA, dw3_w, dw3_b, bufB);
    {
        const int plane = 10 * 32 * 96;
        const int nquad = NB * plane / 4;
        pw_kernel<40, 20, float, float>
            <<<dim3((nquad + 255) / 256, 2), 256>>>(bufB, pw3_w, pw3_b, bufA,
                                                    40, plane, nquad);
    }

    // ---- block 4 (stride 2): dw -> (40,5,16,48), pw 40->80 -> d_out (fp32) ----
    {
        const int threads = NB * 40 * 5 * 16 * (48 / 8);
        dw_s2_kernel<40, 10, 32, 96, 5, 16, 48, float, float>
            <<<(threads + 255) / 256, 256>>>(bufA, dw4_w, dw4_b, bufB);
        const int plane = 5 * 16 * 48;
        const int nquad = NB * plane / 4;
        pw_kernel<40, 20, float, float>
            <<<dim3((nquad + 255) / 256, 4), 256>>>(bufB, pw4_w, pw4_b, out,
                                                    80, plane, nquad);
    }
}

// round 15
// speedup vs baseline: 1.1515x; 1.0303x over previous
#include <cuda_runtime.h>
#include <cuda_fp16.h>
#include <cstdint>

#define NB   8
#define NC   64
#define NH   64
#define NW   192
#define NP   20

__device__ float g_bufA[NB * NP * NP * NH * NW];
__device__ float g_bufB[NB * NP * NP * NH * NW];

__device__ __forceinline__ float leaky(float x) {
    return x > 0.0f ? x : 0.1f * x;
}

// ---- typed vector IO (fp32 or fp16 storage, fp32 compute) -----------------
template<typename T> struct VIO;
template<> struct VIO<float> {
    static __device__ __forceinline__ float4 ld4(const float* p) { return *(const float4*)p; }
    static __device__ __forceinline__ void st4(float* p, float4 v) { *(float4*)p = v; }
    static __device__ __forceinline__ float ld1(const float* p) { return *p; }
};
template<> struct VIO<__half> {
    static __device__ __forceinline__ float4 ld4(const __half* p) {
        uint2 raw = *(const uint2*)p;                 // LDG.64
        __half2 h0 = *reinterpret_cast<__half2*>(&raw.x);
        __half2 h1 = *reinterpret_cast<__half2*>(&raw.y);
        float2 f0 = __half22float2(h0), f1 = __half22float2(h1);
        return make_float4(f0.x, f0.y, f1.x, f1.y);
    }
    static __device__ __forceinline__ void st4(__half* p, float4 v) {
        __half2 h0 = __floats2half2_rn(v.x, v.y);
        __half2 h1 = __floats2half2_rn(v.z, v.w);
        uint2 raw;
        raw.x = *reinterpret_cast<uint32_t*>(&h0);
        raw.y = *reinterpret_cast<uint32_t*>(&h1);
        *(uint2*)p = raw;                             // STG.64
    }
    static __device__ __forceinline__ float ld1(const __half* p) { return __half2float(*p); }
};

// ---- packed f32x2 helpers (sm_103a) --------------------------------------
__device__ __forceinline__ unsigned long long pk2(float lo, float hi) {
    unsigned long long r;
    asm("mov.b64 %0, {%1, %2};" : "=l"(r) : "f"(lo), "f"(hi));
    return r;
}
__device__ __forceinline__ void fma2(unsigned long long& d,
                                     unsigned long long a,
                                     unsigned long long b) {
    asm("fma.rn.f32x2 %0, %1, %2, %0;" : "+l"(d) : "l"(a), "l"(b));
}
__device__ __forceinline__ float2 upk(unsigned long long v) {
    float2 f;
    asm("mov.b64 {%0, %1}, %2;" : "=f"(f.x), "=f"(f.y) : "l"(v));
    return f;
}

// ---------------------------------------------------------------------------
// Correlation: block = (h, di-pair, b), 96 threads = 3 warps, ALL active.
// ---------------------------------------------------------------------------
__global__ void __launch_bounds__(96, 4)
corr_kernel(const float* __restrict__ rgb,
            const float* __restrict__ dep,
            __half* __restrict__ out)
{
    const int h  = blockIdx.x;
    const int dp = blockIdx.y;          // di = 2*dp + r
    const int b  = blockIdx.z;
    const int tid = threadIdx.x;

    __shared__ __align__(16) float sm_rgb[16 * 192];
    __shared__ __align__(16) float sm_dep[2 * 16 * 212];  // [r*16+c][x], x=w+dj

    const int r   = tid / 48;
    const int it  = tid % 48;
    const int wg  = it % 24;
    const int djg = it / 24;
    const int w0  = wg * 8;
    const int dj0 = djg * 10;
    const int x0  = w0 + dj0;           // even

    const int hr0 = h + 2 * dp - 10;
    const int hr1 = hr0 + 1;
    const bool v0 = (hr0 >= 0 && hr0 < NH);
    const bool v1 = (hr1 >= 0 && hr1 < NH);

    if (!v0 && !v1) {
        uint4 z = {0u, 0u, 0u, 0u};
        #pragma unroll
        for (int j = 0; j < 10; j++) {
            size_t base = ((((size_t)b * NP + 2 * dp + r) * NP + dj0 + j) * NH + h) * NW + w0;
            *(uint4*)&out[base] = z;
        }
        return;
    }

    unsigned long long acc2[10][4];
    #pragma unroll
    for (int j = 0; j < 10; j++)
        #pragma unroll
        for (int p = 0; p < 4; p++) acc2[j][p] = 0ull;

    const size_t bbase = (size_t)b * NC * NH * NW;

    #pragma unroll 1
    for (int cc = 0; cc < 4; cc++) {
        const int c0 = cc * 16;
        if (cc) __syncthreads();

        #pragma unroll
        for (int u = 0; u < 8; u++) {
            int i = tid + u * 96;
            int c = i / 48;
            int k4 = (i - c * 48) * 4;
            *(float4*)&sm_rgb[c * 192 + k4] =
                *(const float4*)&rgb[bbase + (size_t)(c0 + c) * (NH * NW) + h * NW + k4];
        }
        #pragma unroll
        for (int u = 0; u < 16; u++) {
            int i = tid + u * 96;
            int rc = i / 48;                 // 0..31
            int k4 = (i - rc * 48) * 4;
            int rr = rc >> 4;
            int c  = rc & 15;
            int hr = rr ? hr1 : hr0;
            bool vr = rr ? v1 : v0;
            float4 v = {0.f, 0.f, 0.f, 0.f};
            if (vr)
                v = *(const float4*)&dep[bbase + (size_t)(c0 + c) * (NH * NW) + hr * NW + k4];
            float* dst = &sm_dep[rc * 212 + 10 + k4];
            *(float2*)(dst)     = make_float2(v.x, v.y);
            *(float2*)(dst + 2) = make_float2(v.z, v.w);
        }
        #pragma unroll
        for (int u = 0; u < 7; u++) {
            int i = tid + u * 96;
            if (i < 640) {
                int rc = i / 20;
                int p = i - rc * 20;
                int x = (p < 10) ? p : 192 + p;
                sm_dep[rc * 212 + x] = 0.0f;
            }
        }
        __syncthreads();

        #pragma unroll 2
        for (int c = 0; c < 16; c++) {
            const unsigned long long* rpu =
                (const unsigned long long*)&sm_rgb[c * 192 + w0];
            unsigned long long r2[4];
            #pragma unroll
            for (int p = 0; p < 4; p++) r2[p] = rpu[p];

            const unsigned long long* dpt =
                (const unsigned long long*)&sm_dep[(r * 16 + c) * 212 + x0];
            unsigned long long dvu[9];
            float2 dvf[9];
            #pragma unroll
            for (int k = 0; k < 9; k++) {
                dvu[k] = dpt[k];
                dvf[k] = upk(dvu[k]);
            }

            #pragma unroll
            for (int m = 0; m < 5; m++) {
                #pragma unroll
                for (int p = 0; p < 4; p++)
                    fma2(acc2[2 * m][p], r2[p], dvu[p + m]);
                #pragma unroll
                for (int p = 0; p < 4; p++) {
                    unsigned long long d = pk2(dvf[p + m].y, dvf[p + m + 1].x);
                    fma2(acc2[2 * m + 1][p], r2[p], d);
                }
            }
        }
    }

    #pragma unroll
    for (int j = 0; j < 10; j++) {
        float2 f0 = upk(acc2[j][0]);
        float2 f1 = upk(acc2[j][1]);
        float2 f2 = upk(acc2[j][2]);
        float2 f3 = upk(acc2[j][3]);
        size_t base = ((((size_t)b * NP + 2 * dp + r) * NP + dj0 + j) * NH + h) * NW + w0;
        __half2 hh[4] = {
            __floats2half2_rn(f0.x, f0.y), __floats2half2_rn(f1.x, f1.y),
            __floats2half2_rn(f2.x, f2.y), __floats2half2_rn(f3.x, f3.y)
        };
        *(uint4*)&out[base] = *(uint4*)hh;
    }
}

// ---------------------------------------------------------------------------
// Depthwise 3x3x3, stride 1, pad 1, + leaky. D-PAIR blocks: each block
// computes outputs d0 and d0+1 from 4 smem z-planes (input read per output
// drops from 3 planes to 2). Packed f32x2 compute, weights in registers.
// ---------------------------------------------------------------------------
template<int C, int D, int H, int W, int HT, typename Tin, typename Tout>
__global__ void __launch_bounds__(256)
dw_s1_kernel(const Tin* __restrict__ in,
             const float* __restrict__ wgt,
             const float* __restrict__ bias,
             Tout* __restrict__ out)
{
    constexpr int SW = W + 8;
    __shared__ float smp[4 * 18 * SW];

    int bx = blockIdx.x;
    const int ht = bx % HT;       bx /= HT;
    const int dpair = bx % (D / 2); bx /= (D / 2);
    const int c  = bx % C;
    const int n  = bx / C;
    const int d0 = dpair * 2;
    const int h0 = ht * 16;
    const int tid = threadIdx.x;

    const Tin* inb = in + (size_t)(n * C + c) * D * H * W;

    constexpr int WQ = W / 4;
    constexpr int nf4 = 4 * 18 * WQ;
    for (int i = tid; i < nf4; i += blockDim.x) {
        int row = i / WQ;
        int k4  = (i - row * WQ) * 4;
        int z = row / 18;
        int y = row - z * 18;
        int zi = d0 - 1 + z, yi = h0 - 1 + y;
        float4 v = {0.f, 0.f, 0.f, 0.f};
        if (zi >= 0 && zi < D && yi >= 0 && yi < H)
            v = VIO<Tin>::ld4(&inb[(size_t)zi * H * W + yi * W + k4]);
        *(float4*)&smp[row * SW + 4 + k4] = v;
    }
    for (int i = tid; i < 4 * 18 * 8; i += blockDim.x) {
        int row = i / 8;
        int p   = i - row * 8;
        int x   = (p < 4) ? p : W + p;
        smp[row * SW + x] = 0.0f;
    }

    unsigned long long wt2[27];
    #pragma unroll
    for (int k = 0; k < 27; k++) {
        float wv = __ldg(&wgt[c * 27 + k]);
        wt2[k] = pk2(wv, wv);
    }
    const float bb = __ldg(&bias[c]);
    const unsigned long long bb2 = pk2(bb, bb);
    __syncthreads();

    constexpr int items = 2 * 16 * WQ;
    for (int it = tid; it < items; it += blockDim.x) {
        int dd  = it / (16 * WQ);
        int rem = it - dd * (16 * WQ);
        int hl  = rem / WQ;
        int wg4 = (rem - hl * WQ) * 4;
        unsigned long long A01 = bb2, A23 = bb2;
        #pragma unroll
        for (int z = 0; z < 3; z++)
            #pragma unroll
            for (int y = 0; y < 3; y++) {
                const float* row = &smp[((dd + z) * 18 + hl + y) * SW];
                float m1  = row[wg4 + 3];
                float4 v4 = *(const float4*)&row[wg4 + 4];
                float pr  = row[wg4 + 8];
                unsigned long long dv0 = pk2(m1,   v4.x);
                unsigned long long dv1 = pk2(v4.x, v4.y);
                unsigned long long dv2 = pk2(v4.y, v4.z);
                unsigned long long dv3 = pk2(v4.z, v4.w);
                unsigned long long dv4 = pk2(v4.w, pr);
                const int kb = (z * 3 + y) * 3;
                fma2(A01, wt2[kb + 0], dv0);
                fma2(A01, wt2[kb + 1], dv1);
                fma2(A01, wt2[kb + 2], dv2);
                fma2(A23, wt2[kb + 0], dv2);
                fma2(A23, wt2[kb + 1], dv3);
                fma2(A23, wt2[kb + 2], dv4);
            }
        float2 f01 = upk(A01);
        float2 f23 = upk(A23);
        float4 o = {leaky(f01.x), leaky(f01.y), leaky(f23.x), leaky(f23.y)};
        VIO<Tout>::st4(&out[((size_t)(n * C + c) * D + (d0 + dd)) * H * W
                            + (h0 + hl) * W + wg4], o);
    }
}

// ---------------------------------------------------------------------------
// Depthwise 3x3x3, stride 2, pad 1, + leaky. Thread = 8 consecutive wo.
// ---------------------------------------------------------------------------
template<int C, int D, int H, int W, int Do, int Ho, int Wo, typename Tin, typename Tout>
__global__ void dw_s2_kernel(const Tin* __restrict__ in,
                             const float* __restrict__ wgt,
                             const float* __restrict__ bias,
                             Tout* __restrict__ out)
{
    constexpr int WO8 = Wo / 8;
    constexpr int total = NB * C * Do * Ho * WO8;
    int idx = blockIdx.x * blockDim.x + threadIdx.x;
    if (idx >= total) return;
    int t = idx;
    const int q  = t % WO8; t /= WO8;
    const int ho = t % Ho; t /= Ho;
    const int dd = t % Do; t /= Do;
    const int c  = t % C;
    const int n  = t / C;
    const int g  = q * 16;               // input x base (= 2*wo0)

    const Tin* inb = in + (size_t)(n * C + c) * D * H * W;
    const float* wp  = &wgt[c * 27];
    const float bb = __ldg(&bias[c]);
    float a[8];
    #pragma unroll
    for (int k = 0; k < 8; k++) a[k] = bb;

    #pragma unroll
    for (int kz = 0; kz < 3; kz++) {
        int zi = 2 * dd - 1 + kz;
        if (zi < 0 || zi >= D) continue;
        #pragma unroll
        for (int ky = 0; ky < 3; ky++) {
            int yi = 2 * ho - 1 + ky;
            if (yi < 0 || yi >= H) continue;
            const Tin* base = &inb[(size_t)zi * H * W + yi * W];
            float m1 = (g > 0) ? VIO<Tin>::ld1(&base[g - 1]) : 0.0f;
            float4 v0 = VIO<Tin>::ld4(&base[g]);
            float4 v1 = VIO<Tin>::ld4(&base[g + 4]);
            float4 v2 = VIO<Tin>::ld4(&base[g + 8]);
            float4 v3 = VIO<Tin>::ld4(&base[g + 12]);
            float xv[17] = {m1,
                            v0.x, v0.y, v0.z, v0.w,
                            v1.x, v1.y, v1.z, v1.w,
                            v2.x, v2.y, v2.z, v2.w,
                            v3.x, v3.y, v3.z, v3.w};
            float w0 = __ldg(&wp[(kz * 3 + ky) * 3 + 0]);
            float w1 = __ldg(&wp[(kz * 3 + ky) * 3 + 1]);
            float w2 = __ldg(&wp[(kz * 3 + ky) * 3 + 2]);
            #pragma unroll
            for (int k = 0; k < 8; k++)
                a[k] += w0 * xv[2 * k] + w1 * xv[2 * k + 1] + w2 * xv[2 * k + 2];
        }
    }
    size_t obase = ((((size_t)n * C + c) * Do + dd) * Ho + ho) * Wo + q * 8;
    float4 o0 = {leaky(a[0]), leaky(a[1]), leaky(a[2]), leaky(a[3])};
    float4 o1 = {leaky(a[4]), leaky(a[5]), leaky(a[6]), leaky(a[7])};
    VIO<Tout>::st4(&out[obase], o0);
    VIO<Tout>::st4(&out[obase + 4], o1);
}

// ---------------------------------------------------------------------------
// Pointwise Cin->Cout + leaky. f32x2 accumulators, packed duplicated weights.
// ---------------------------------------------------------------------------
template<int Cin, int COT, typename Tin, typename Tout>
__global__ void pw_kernel(const Tin* __restrict__ in,
                          const float* __restrict__ wgt,
                          const float* __restrict__ bias,
                          Tout* __restrict__ out,
                          int Cout, int plane, int nquad)
{
    __shared__ unsigned long long sw2[COT * Cin];
    __shared__ float sb[COT];

    const int co0 = blockIdx.y * COT;
    const int tid = threadIdx.x;

    for (int i = tid; i < COT * Cin; i += blockDim.x) {
        int j  = i / Cin;
        int ci = i - j * Cin;
        float wv = wgt[(co0 + j) * Cin + ci];
        sw2[i] = pk2(wv, wv);
    }
    if (tid < COT) sb[tid] = bias[co0 + tid];
    __syncthreads();

    const int t = blockIdx.x * blockDim.x + tid;
    if (t >= nquad) return;
    const int s0 = t * 4;
    const int n  = s0 / plane;
    const int p  = s0 - n * plane;

    const Tin* inb = in + (size_t)n * Cin * plane + p;

    unsigned long long acc2[COT][2];
    #pragma unroll
    for (int j = 0; j < COT; j++) {
        float bv = sb[j];
        unsigned long long bp = pk2(bv, bv);
        acc2[j][0] = bp; acc2[j][1] = bp;
    }

    #pragma unroll
    for (int ci = 0; ci < Cin; ci++) {
        float4 x4 = VIO<Tin>::ld4(&inb[(size_t)ci * plane]);
        unsigned long long xa = pk2(x4.x, x4.y);
        unsigned long long xb = pk2(x4.z, x4.w);
        #pragma unroll
        for (int j = 0; j < COT; j++) {
            unsigned long long wv2 = sw2[j * Cin + ci];
            fma2(acc2[j][0], wv2, xa);
            fma2(acc2[j][1], wv2, xb);
        }
    }

    Tout* ob = out + (size_t)n * Cout * plane + p;
    #pragma unroll
    for (int j = 0; j < COT; j++) {
        float2 fa = upk(acc2[j][0]);
        float2 fb = upk(acc2[j][1]);
        float4 o = {leaky(fa.x), leaky(fa.y), leaky(fb.x), leaky(fb.y)};
        VIO<Tout>::st4(&ob[(size_t)(co0 + j) * plane], o);
    }
}

// ---------------------------------------------------------------------------
extern "C" void kernel_launch(void* const* d_in, const int* in_sizes, int n_in,
                              void* d_out, int out_size)
{
    const float* rgb   = (const float*)d_in[0];
    const float* dep   = (const float*)d_in[1];
    const float* dw1_w = (const float*)d_in[2];
    const float* dw1_b = (const float*)d_in[3];
    const float* pw1_w = (const float*)d_in[4];
    const float* pw1_b = (const float*)d_in[5];
    const float* dw2_w = (const float*)d_in[6];
    const float* dw2_b = (const float*)d_in[7];
    const float* pw2_w = (const float*)d_in[8];
    const float* pw2_b = (const float*)d_in[9];
    const float* dw3_w = (const float*)d_in[10];
    const float* dw3_b = (const float*)d_in[11];
    const float* pw3_w = (const float*)d_in[12];
    const float* pw3_b = (const float*)d_in[13];
    const float* dw4_w = (const float*)d_in[14];
    const float* dw4_b = (const float*)d_in[15];
    const float* pw4_w = (const float*)d_in[16];
    const float* pw4_b = (const float*)d_in[17];
    float* out = (float*)d_out;

    float *bufA = nullptr, *bufB = nullptr;
    cudaGetSymbolAddress((void**)&bufA, g_bufA);
    cudaGetSymbolAddress((void**)&bufB, g_bufB);
    __half* bufA_h = (__half*)bufA;
    __half* bufB_h = (__half*)bufB;

    // ---- correlation -> bufA (fp16) ----
    corr_kernel<<<dim3(NH, NP / 2, NB), 96>>>(rgb, dep, bufA_h);

    // ---- block 1 (stride 1): dw 20ch d-pair (fp16->fp16), pw 20->20 ----
    dw_s1_kernel<20, 20, 64, 192, 4, __half, __half>
        <<<NB * 20 * 10 * 4, 256>>>(bufA_h, dw1_w, dw1_b, bufB_h);
    {
        const int plane = 20 * 64 * 192;
        const int nquad = NB * plane / 4;
        pw_kernel<20, 20, __half, __half>
            <<<dim3((nquad + 255) / 256, 1), 256>>>(bufB_h, pw1_w, pw1_b, bufA_h,
                                                    20, plane, nquad);
    }

    // ---- block 2 (stride 2): dw (fp16->fp32) -> (20,10,32,96), pw 20->40 ----
    {
        const int threads = NB * 20 * 10 * 32 * (96 / 8);
        dw_s2_kernel<20, 20, 64, 192, 10, 32, 96, __half, float>
            <<<(threads + 255) / 256, 256>>>(bufA_h, dw2_w, dw2_b, bufB);
        const int plane = 10 * 32 * 96;
        const int nquad = NB * plane / 4;
        pw_kernel<20, 20, float, float>
            <<<dim3((nquad + 255) / 256, 2), 256>>>(bufB, pw2_w, pw2_b, bufA,
                                                    40, plane, nquad);
    }

    // ---- block 3 (stride 1): dw 40ch d-pair on (10,32,96), pw 40->40 ----
    dw_s1_kernel<40, 10, 32, 96, 2, float, float>
        <<<NB * 40 * 5 * 2, 256>>>(bufA, dw3_w, dw3_b, bufB);
    {
        const int plane = 10 * 32 * 96;
        const int nquad = NB * plane / 4;
        pw_kernel<40, 20, float, float>
            <<<dim3((nquad + 255) / 256, 2), 256>>>(bufB, pw3_w, pw3_b, bufA,
                                                    40, plane, nquad);
    }

    // ---- block 4 (stride 2): dw -> (40,5,16,48), pw 40->80 -> d_out ----
    {
        const int threads = NB * 40 * 5 * 16 * (48 / 8);
        dw_s2_kernel<40, 10, 32, 96, 5, 16, 48, float, float>
            <<<(threads + 255) / 256, 256>>>(bufA, dw4_w, dw4_b, bufB);
        const int plane = 5 * 16 * 48;
        const int nquad = NB * plane / 4;
        pw_kernel<40, 20, float, float>
            <<<dim3((nquad + 255) / 256, 4), 256>>>(bufB, pw4_w, pw4_b, out,
                                                    80, plane, nquad);
    }
}